// round 15
// speedup vs baseline: 2.8357x; 1.0498x over previous
#include <cuda_runtime.h>

#define NB   2
#define NF   8192
#define DIMM 512
#define NH   8
#define DH   64
#define LM   256
#define QD   1536
#define TOT  (NB*NF)    // 16384
#define NBH  (NB*NH)    // 16
#define KER  33
#define KSPL 8

// ------------------------- scratch (device globals, no allocs) -------------
__device__ float g_X  [TOT*DIMM];
__device__ float g_XN [TOT*DIMM];
__device__ float g_QKV[TOT*QD];
__device__ float g_QL [NBH*LM*DH];
__device__ float g_KL [NBH*LM*DH];
__device__ float g_S3 [NBH*LM*NF];
__device__ float g_S2 [NBH*LM*LM];
__device__ float g_Zb [NBH*LM*LM];
__device__ float g_Z2b[NBH*LM*LM];
__device__ float g_Pb [NBH*LM*LM];
__device__ float g_Tb [NBH*LM*LM];
__device__ float g_T2b[NBH*LM*LM];
__device__ float g_AV [NBH*LM*DH];
__device__ float g_AVp[NBH*KSPL*LM*DH];
__device__ float g_ZAV[NBH*LM*DH];
__device__ float g_OH [NBH*NF*DH];
__device__ float g_WT [2621440];
__device__ float2 g_RS3[NBH*LM];
__device__ float2 g_RSp[NBH*LM*64];
__device__ unsigned int g_scale[2];
__device__ unsigned int g_bar;

enum { EP_NONE = 0, EP_RELU_REMAP = 1, EP_SCALEQ = 2, EP_ADDBIAS = 3 };

#define OW1   0
#define OQKV(L) (524288 + (L) * 786432)
#define OOUT(L) (2097152 + (L) * 262144)

__device__ __forceinline__ unsigned f2tf32(float f) {
    unsigned r;
    asm("cvt.rna.tf32.f32 %0, %1;" : "=r"(r) : "f"(f));
    return r;
}
__device__ __forceinline__ float tf32f(float f) {
    return __uint_as_float(f2tf32(f));
}

#define MMA_TF32(d, a, b) \
    asm volatile("mma.sync.aligned.m16n8k8.row.col.f32.tf32.tf32.f32 " \
        "{%0,%1,%2,%3}, {%4,%5,%6,%7}, {%8,%9}, {%0,%1,%2,%3};" \
        : "+f"((d)[0]), "+f"((d)[1]), "+f"((d)[2]), "+f"((d)[3]) \
        : "r"((a)[0]), "r"((a)[1]), "r"((a)[2]), "r"((a)[3]), \
          "r"((b)[0]), "r"((b)[1]))

#define LDMX4(v, ad) \
    asm volatile("ldmatrix.sync.aligned.m8n8.x4.shared.b16 {%0,%1,%2,%3}, [%4];" \
        : "=r"((v)[0]), "=r"((v)[1]), "=r"((v)[2]), "=r"((v)[3]) : "r"(ad))

// ------------------------- reductions --------------------------------------
__device__ __forceinline__ float blockReduce(float v, bool domax) {
    __shared__ float sh[32];
    __syncthreads();
    #pragma unroll
    for (int o = 16; o > 0; o >>= 1) {
        float w = __shfl_down_sync(0xffffffffu, v, o);
        v = domax ? fmaxf(v, w) : v + w;
    }
    int lane = threadIdx.x & 31, wid = threadIdx.x >> 5;
    if (lane == 0) sh[wid] = v;
    __syncthreads();
    int nw = (blockDim.x + 31) >> 5;
    if (wid == 0) {
        v = (lane < nw) ? sh[lane] : (domax ? -1e30f : 0.f);
        #pragma unroll
        for (int o = 16; o > 0; o >>= 1) {
            float w = __shfl_down_sync(0xffffffffu, v, o);
            v = domax ? fmaxf(v, w) : v + w;
        }
        if (lane == 0) sh[0] = v;
    }
    __syncthreads();
    return sh[0];
}

// ------------------- fused transposes + cls (ONE launch) --------------------
__device__ __forceinline__ void doTrans(const float* __restrict__ src,
                                        float* __restrict__ dst,
                                        int K, int N, int kt, int nt)
{
    __shared__ float t[32][33];
    int kb = kt << 5, nb = nt << 5;
    int x = threadIdx.x & 31, y = threadIdx.x >> 5;
    #pragma unroll
    for (int i = 0; i < 32; i += 8)
        t[y + i][x] = src[(long long)(kb + y + i) * N + nb + x];
    __syncthreads();
    #pragma unroll
    for (int i = 0; i < 32; i += 8)
        dst[(long long)(nb + y + i) * K + kb + x] = t[x][y + i];
}

__global__ void __launch_bounds__(256) transAll_k(
    const float* __restrict__ w1, const float* __restrict__ wqkv,
    const float* __restrict__ wout, const float* __restrict__ clst)
{
    int b = blockIdx.x;
    if (b < 512) {
        doTrans(w1, g_WT + OW1, 1024, DIMM, b & 31, b >> 5);
    } else if (b < 2048) {
        int L = (b - 512) / 768, bb = (b - 512) % 768;
        doTrans(wqkv + (long long)L * DIMM * QD, g_WT + OQKV(L), DIMM, QD, bb & 15, bb >> 4);
    } else if (b < 2560) {
        int L = (b - 2048) / 256, bb = (b - 2048) % 256;
        doTrans(wout + (long long)L * DIMM * DIMM, g_WT + OOUT(L), DIMM, DIMM, bb & 15, bb >> 4);
    } else {
        int idx = (b - 2560) * 256 + threadIdx.x;
        int bb = idx >> 9, c = idx & 511;
        g_X[(long long)bb * NF * DIMM + c] = clst[c];
    }
}

// ======= mgemm2: cp.async + ldmatrix tf32, 128x128, 3-stage, 2 CTA/SM =======
__device__ __forceinline__ void cp16(unsigned dst, const void* src, int nbytes) {
    asm volatile("cp.async.cg.shared.global [%0], [%1], 16, %2;"
                 :: "r"(dst), "l"(src), "r"(nbytes) : "memory");
}

template<int STAT>
__global__ void __launch_bounds__(256, 2) mgemm2_k(
    int M, int K,
    const float* __restrict__ A, int lda, long long sA1, long long sA2, int amode,
    const float* __restrict__ BT, int ldbt, long long sBT1, long long sBT2,
    float* __restrict__ C, int ldc, long long sC1, long long sC2,
    int ep, const float* __restrict__ bias,
    float2* __restrict__ RSp, long long rsp1, long long rsp2)
{
    extern __shared__ float smem[];   // 3 stages x 32KB = 96KB
    int tid = threadIdx.x;
    int lane = tid & 31, wid = tid >> 5;
    int wm = wid & 3, wn = wid >> 2;
    int row0 = blockIdx.y << 7, col0 = blockIdx.x << 7;
    int z = blockIdx.z;
    A  += (long long)(z >> 3) * sA1 + (long long)(z & 7) * sA2;
    BT += (long long)(z >> 3) * sBT1 + (long long)(z & 7) * sBT2;
    C  += (long long)(z >> 3) * sC1 + (long long)(z & 7) * sC2;
    if (STAT) RSp += (long long)(z >> 3) * rsp1 + (long long)(z & 7) * rsp2;

    unsigned sbase;
    asm("{ .reg .u64 t; cvta.to.shared.u64 t, %1; cvt.u32.u64 %0, t; }"
        : "=r"(sbase) : "l"(smem));

    float acc[2][8][4];
    #pragma unroll
    for (int mi = 0; mi < 2; mi++)
        #pragma unroll
        for (int ni = 0; ni < 8; ni++)
            #pragma unroll
            for (int q = 0; q < 4; q++) acc[mi][ni][q] = 0.f;

    auto fill = [&](int s, int k0) {
        unsigned Ab = sbase + s * 32768u;
        unsigned Bb = Ab + 16384u;
        #pragma unroll
        for (int it = 0; it < 4; it++) {
            int idx = (it << 8) + tid;
            int q = idx & 7, r = idx >> 3;
            int gr = row0 + r;
            const float* src;
            int nb = 16;
            if (amode == 0) {
                int gra = gr < M ? gr : (M - 1);
                if (gr >= M) nb = 0;
                src = A + (long long)gra * lda + k0 + (q << 2);
            } else {
                int k = k0 + (q << 2);
                int h = k >> 6, d = k & 63;
                src = A + ((((long long)(gr >> 13) << 3) + h) * 8192 + (gr & 8191)) * 64 + d;
            }
            unsigned dst = Ab + (((r << 5) + ((q ^ (r & 7)) << 2)) << 2);
            cp16(dst, src, nb);
        }
        #pragma unroll
        for (int it = 0; it < 4; it++) {
            int idx = (it << 8) + tid;
            int q = idx & 7, n = idx >> 3;
            const float* src = BT + (long long)(col0 + n) * ldbt + k0 + (q << 2);
            unsigned dst = Bb + (((n << 5) + ((q ^ (n & 7)) << 2)) << 2);
            cp16(dst, src, 16);
        }
        asm volatile("cp.async.commit_group;" ::: "memory");
    };

    auto compute = [&](int s) {
        unsigned Ab = sbase + s * 32768u;
        unsigned Bb = Ab + 16384u;
        int j = lane >> 3, rho = lane & 7;
        #pragma unroll
        for (int kt = 0; kt < 4; kt++) {
            unsigned a[2][4];
            #pragma unroll
            for (int mi = 0; mi < 2; mi++) {
                int row = (wm << 5) + (mi << 4) + ((j & 1) << 3) + rho;
                int quad = (kt << 1) + (j >> 1);
                unsigned ad = Ab + (((row << 5) + ((quad ^ (row & 7)) << 2)) << 2);
                LDMX4(a[mi], ad);
            }
            unsigned b[8][2];
            #pragma unroll
            for (int np = 0; np < 4; np++) {
                int row = (((wn << 3) + (np << 1) + (j >> 1)) << 3) + rho;
                int quad = (kt << 1) + (j & 1);
                unsigned bd = Bb + (((row << 5) + ((quad ^ (row & 7)) << 2)) << 2);
                unsigned v[4];
                LDMX4(v, bd);
                b[np * 2][0] = v[0]; b[np * 2][1] = v[1];
                b[np * 2 + 1][0] = v[2]; b[np * 2 + 1][1] = v[3];
            }
            #pragma unroll
            for (int mi = 0; mi < 2; mi++)
                #pragma unroll
                for (int ni = 0; ni < 8; ni++)
                    MMA_TF32(acc[mi][ni], a[mi], b[ni]);
        }
    };

    int nch = K >> 5;
    fill(0, 0);
    if (nch > 1) fill(1, 32);
    for (int ch = 0; ch < nch; ch++) {
        if (ch + 1 < nch)
            asm volatile("cp.async.wait_group 1;" ::: "memory");
        else
            asm volatile("cp.async.wait_group 0;" ::: "memory");
        __syncthreads();
        if (ch + 2 < nch) fill((ch + 2) % 3, (ch + 2) << 5);
        compute(ch % 3);
    }

    int rb = row0 + (wm << 5) + (lane >> 2);
    int cb = col0 + (wn << 6) + ((lane & 3) << 1);
    #pragma unroll
    for (int mi = 0; mi < 2; mi++) {
        #pragma unroll
        for (int half = 0; half < 2; half++) {
            int r = rb + (mi << 4) + (half << 3);
            if (r >= M) continue;
            #pragma unroll
            for (int ni = 0; ni < 8; ni++) {
                int c = cb + (ni << 3);
                float v0 = acc[mi][ni][half * 2];
                float v1 = acc[mi][ni][half * 2 + 1];
                if (ep == EP_RELU_REMAP) {
                    long long o = (long long)(r + r / 8191 + 1) * ldc + c;
                    v0 = fmaxf(v0 + bias[c], 0.f);
                    v1 = fmaxf(v1 + bias[c + 1], 0.f);
                    *(float2*)(C + o) = make_float2(v0, v1);
                } else if (ep == EP_SCALEQ) {
                    float sc = (c < 512) ? 0.125f : 1.0f;
                    *(float2*)(C + (long long)r * ldc + c) = make_float2(v0 * sc, v1 * sc);
                } else if (ep == EP_ADDBIAS) {
                    long long o = (long long)r * ldc + c;
                    float2 old = *(float2*)(C + o);
                    *(float2*)(C + o) = make_float2(old.x + v0 + bias[c],
                                                    old.y + v1 + bias[c + 1]);
                } else {
                    *(float2*)(C + (long long)r * ldc + c) = make_float2(v0, v1);
                }
            }
        }
    }

    if (STAT) {
        float* red = smem;
        int g = lane >> 2;
        float rowm[2][2];
        __syncthreads();
        #pragma unroll
        for (int mi = 0; mi < 2; mi++) {
            #pragma unroll
            for (int half = 0; half < 2; half++) {
                float m = -1e30f;
                #pragma unroll
                for (int ni = 0; ni < 8; ni++)
                    m = fmaxf(m, fmaxf(acc[mi][ni][half * 2], acc[mi][ni][half * 2 + 1]));
                m = fmaxf(m, __shfl_xor_sync(0xffffffffu, m, 1));
                m = fmaxf(m, __shfl_xor_sync(0xffffffffu, m, 2));
                if ((lane & 3) == 0) {
                    int rl = (wm << 5) + (mi << 4) + (half << 3) + g;
                    red[rl * 2 + wn] = m;
                }
            }
        }
        __syncthreads();
        #pragma unroll
        for (int mi = 0; mi < 2; mi++) {
            #pragma unroll
            for (int half = 0; half < 2; half++) {
                int rl = (wm << 5) + (mi << 4) + (half << 3) + g;
                rowm[mi][half] = fmaxf(red[rl * 2], red[rl * 2 + 1]);
            }
        }
        __syncthreads();
        #pragma unroll
        for (int mi = 0; mi < 2; mi++) {
            #pragma unroll
            for (int half = 0; half < 2; half++) {
                float m = rowm[mi][half];
                float s = 0.f;
                #pragma unroll
                for (int ni = 0; ni < 8; ni++)
                    s += __expf(acc[mi][ni][half * 2] - m) + __expf(acc[mi][ni][half * 2 + 1] - m);
                s += __shfl_xor_sync(0xffffffffu, s, 1);
                s += __shfl_xor_sync(0xffffffffu, s, 2);
                if ((lane & 3) == 0) {
                    int rl = (wm << 5) + (mi << 4) + (half << 3) + g;
                    red[256 + rl * 2 + wn] = s;
                }
            }
        }
        __syncthreads();
        if (wn == 0 && (lane & 3) == 0) {
            #pragma unroll
            for (int mi = 0; mi < 2; mi++) {
                #pragma unroll
                for (int half = 0; half < 2; half++) {
                    int rl = (wm << 5) + (mi << 4) + (half << 3) + g;
                    int gr = row0 + rl;
                    if (gr < M)
                        RSp[(long long)gr * gridDim.x + blockIdx.x] =
                            make_float2(rowm[mi][half],
                                        red[256 + rl * 2] + red[256 + rl * 2 + 1]);
                }
            }
        }
    }
}

// ------------------------- combine softmax partials -------------------------
__global__ void __launch_bounds__(256) combine_k(const float2* __restrict__ RSp,
                                                 float2* __restrict__ RS, int nblk)
{
    int row = blockIdx.x * 8 + (threadIdx.x >> 5);
    int lane = threadIdx.x & 31;
    const float2* p = RSp + (long long)row * nblk;
    float m = -1e30f;
    for (int i = lane; i < nblk; i += 32) m = fmaxf(m, p[i].x);
    #pragma unroll
    for (int o = 16; o > 0; o >>= 1) m = fmaxf(m, __shfl_xor_sync(0xffffffffu, m, o));
    float s = 0.f;
    for (int i = lane; i < nblk; i += 32) {
        float2 v = p[i];
        s += v.y * __expf(v.x - m);
    }
    #pragma unroll
    for (int o = 16; o > 0; o >>= 1) s += __shfl_xor_sync(0xffffffffu, s, o);
    if (lane == 0) RS[row] = make_float2(m, 1.f / s);
}

// ===================== agemm: tf32 GEMM, 128xN64 tile, exp-fused A ==========
__global__ void __launch_bounds__(256, 2) agemm_k(
    int M, int K,
    const float* __restrict__ A, int lda, long long sA1, long long sA2, long long sA3,
    const float* __restrict__ B, int ldb, long long sB1, long long sB2, long long sB3,
    float* __restrict__ C, long long sC1, long long sC2, long long sC3,
    int SPLIT, float alpha,
    const float2* __restrict__ rsA, long long rs1, long long rs2, int aexp)
{
    extern __shared__ unsigned dsm[];
    int z = blockIdx.z;
    int s = z % SPLIT;
    int bh = z / SPLIT;
    int hh = bh & 7, bb = bh >> 3;
    A   += (long long)bb * sA1 + (long long)hh * sA2 + (long long)s * sA3;
    B   += (long long)bb * sB1 + (long long)hh * sB2 + (long long)s * sB3;
    C   += (long long)bb * sC1 + (long long)hh * sC2 + (long long)s * sC3;
    rsA += bb * rs1 + hh * rs2;
    int row0 = blockIdx.y << 7;
    int tid = threadIdx.x, lane = tid & 31, wm = tid >> 5;

    unsigned sbase;
    asm("{ .reg .u64 t; cvta.to.shared.u64 t, %1; cvt.u32.u64 %0, t; }"
        : "=r"(sbase) : "l"(dsm));
    float* Bsm = (float*)(dsm + 8192);

    float acc[8][4];
    #pragma unroll
    for (int ni = 0; ni < 8; ni++)
        #pragma unroll
        for (int q = 0; q < 4; q++) acc[ni][q] = 0.f;

    int a_q = tid & 7, a_r0 = tid >> 3;
    int b_n = tid & 63, b_kh = tid >> 6;

    float4 pa[4];
    float pbv[8];

    auto fetch = [&](int k0) {
        #pragma unroll
        for (int it = 0; it < 4; it++) {
            int r = a_r0 + (it << 5);
            int gr = row0 + r;
            float4 v = *(const float4*)(A + (long long)gr * lda + k0 + (a_q << 2));
            if (aexp) {
                float2 st = rsA[gr];
                v.x = __expf(v.x - st.x) * st.y;
                v.y = __expf(v.y - st.x) * st.y;
                v.z = __expf(v.z - st.x) * st.y;
                v.w = __expf(v.w - st.x) * st.y;
            }
            pa[it] = v;
        }
        #pragma unroll
        for (int j = 0; j < 8; j++) {
            int k = (b_kh << 3) + j;
            pbv[j] = B[(long long)(k0 + k) * ldb + b_n];
        }
    };

    auto stash = [&](int st) {
        unsigned* Ab = dsm + st * 4096;
        #pragma unroll
        for (int it = 0; it < 4; it++) {
            int r = a_r0 + (it << 5);
            uint4 u;
            u.x = f2tf32(pa[it].x); u.y = f2tf32(pa[it].y);
            u.z = f2tf32(pa[it].z); u.w = f2tf32(pa[it].w);
            *(uint4*)&Ab[(r << 5) + ((a_q ^ (r & 7)) << 2)] = u;
        }
        float* Bb = Bsm + st * 2112;
        #pragma unroll
        for (int j = 0; j < 8; j++) {
            int k = (b_kh << 3) + j;
            Bb[b_n * 33 + k] = tf32f(pbv[j]);
        }
    };

    auto compute = [&](int st) {
        unsigned Ab = sbase + st * 16384u;
        const float* Bb = Bsm + st * 2112;
        int j = lane >> 3, rho = lane & 7;
        int g = lane >> 2, t = lane & 3;
        #pragma unroll
        for (int kt = 0; kt < 4; kt++) {
            unsigned a[4];
            {
                int row = (wm << 4) + ((j & 1) << 3) + rho;
                int quad = (kt << 1) + (j >> 1);
                unsigned ad = Ab + (((row << 5) + ((quad ^ (row & 7)) << 2)) << 2);
                LDMX4(a, ad);
            }
            #pragma unroll
            for (int ni = 0; ni < 8; ni++) {
                int n = (ni << 3) + g;
                unsigned b[2];
                b[0] = __float_as_uint(Bb[n * 33 + (kt << 3) + t]);
                b[1] = __float_as_uint(Bb[n * 33 + (kt << 3) + t + 4]);
                MMA_TF32(acc[ni], a, b);
            }
        }
    };

    fetch(0);
    int nch = K >> 5;
    for (int ch = 0; ch < nch; ch++) {
        stash(ch & 1);
        __syncthreads();
        if (ch + 1 < nch) fetch((ch + 1) << 5);
        compute(ch & 1);
        __syncthreads();
    }

    int g = lane >> 2, t = lane & 3;
    #pragma unroll
    for (int half = 0; half < 2; half++) {
        int r = row0 + (wm << 4) + (half << 3) + g;
        #pragma unroll
        for (int ni = 0; ni < 8; ni++) {
            int c = (ni << 3) + (t << 1);
            *(float2*)(C + (long long)r * 64 + c) =
                make_float2(acc[ni][half * 2] * alpha, acc[ni][half * 2 + 1] * alpha);
        }
    }
}

// ========== fOH: fused OH = softmax(Q @ KL^T) @ ZAV (exact, per-CTA) ========
// grid (64 row-tiles, 16 bh); 1 CTA/SM; smem 224KB.
__global__ void __launch_bounds__(256, 1) fOH_k(
    const float* __restrict__ QKV, const float* __restrict__ KL,
    const float* __restrict__ ZAV, float* __restrict__ OH)
{
    extern __shared__ float fs[];
    int tid = threadIdx.x, lane = tid & 31, wid = tid >> 5;
    int row0 = blockIdx.x << 7;
    int bh = blockIdx.y;
    int b = bh >> 3, h = bh & 7;
    const float* Qb = QKV + ((long long)b * NF) * QD + h * 64;
    KL  += (long long)bh * LM * DH;
    ZAV += (long long)bh * LM * DH;
    OH  += (long long)bh * NF * DH;

    unsigned sbase;
    asm("{ .reg .u64 t; cvta.to.shared.u64 t, %1; cvt.u32.u64 %0, t; }"
        : "=r"(sbase) : "l"(fs));
    const unsigned Soff = 0, R1off = 32768u, Qoff = 49152u;
    float* redm = fs + 50176;
    float* reds = fs + 50688;
    float* stm  = fs + 51200;
    float* sti  = fs + 51328;

    // ---- stage Q (128x64) and KL (256x64) ----
    {
        #pragma unroll
        for (int it = 0; it < 8; it++) {
            int idx = (it << 8) + tid;
            int q4 = idx & 15, r = idx >> 4;
            float4 v = *(const float4*)(Qb + (long long)(row0 + r) * QD + (q4 << 2));
            int ch = q4 >> 3, q = q4 & 7;
            *(float4*)&fs[Qoff + (ch << 12) + (r << 5) + ((q ^ (r & 7)) << 2)] = v;
        }
        #pragma unroll
        for (int it = 0; it < 16; it++) {
            int idx = (it << 8) + tid;
            int q = idx & 7, n = (idx >> 3) & 255, ch = idx >> 11;
            float4 v = *(const float4*)(KL + (long long)n * 64 + (ch << 5) + (q << 2));
            *(float4*)&fs[R1off + (ch << 13) + (n << 5) + ((q ^ (n & 7)) << 2)] = v;
        }
    }
    __syncthreads();

    // ---- phase 1: S = Q @ KL^T (128 x 256) ----
    int wm = wid & 3, wn = wid >> 2;
    int j = lane >> 3, rho = lane & 7;
    int g = lane >> 2, t4 = lane & 3;
    float acc1[2][2][8][4];
    #pragma unroll
    for (int nh = 0; nh < 2; nh++)
        #pragma unroll
        for (int mi = 0; mi < 2; mi++)
            #pragma unroll
            for (int ni = 0; ni < 8; ni++)
                #pragma unroll
                for (int q = 0; q < 4; q++) acc1[nh][mi][ni][q] = 0.f;

    #pragma unroll
    for (int ch = 0; ch < 2; ch++) {
        #pragma unroll
        for (int kt = 0; kt < 4; kt++) {
            unsigned a[2][4];
            #pragma unroll
            for (int mi = 0; mi < 2; mi++) {
                int row = (wm << 5) + (mi << 4) + ((j & 1) << 3) + rho;
                int quad = (kt << 1) + (j >> 1);
                LDMX4(a[mi], sbase + ((Qoff + (ch << 12) + (row << 5) + ((quad ^ (row & 7)) << 2)) << 2));
            }
            #pragma unroll
            for (int nh = 0; nh < 2; nh++) {
                unsigned bfr[8][2];
                #pragma unroll
                for (int np = 0; np < 4; np++) {
                    int row = (nh << 7) + ((((wn << 3) + (np << 1) + (j >> 1))) << 3) + rho;
                    int quad = (kt << 1) + (j & 1);
                    unsigned v[4];
                    LDMX4(v, sbase + ((R1off + (ch << 13) + (row << 5) + ((quad ^ (row & 7)) << 2)) << 2));
                    bfr[np * 2][0] = v[0]; bfr[np * 2][1] = v[1];
                    bfr[np * 2 + 1][0] = v[2]; bfr[np * 2 + 1][1] = v[3];
                }
                #pragma unroll
                for (int mi = 0; mi < 2; mi++)
                    #pragma unroll
                    for (int ni = 0; ni < 8; ni++)
                        MMA_TF32(acc1[nh][mi][ni], a[mi], bfr[ni]);
            }
        }
    }
    __syncthreads();

    // ---- epilogue: raw S -> Ssm (phase-2-A layout) + per-row stats ----
    #pragma unroll
    for (int nh = 0; nh < 2; nh++) {
        #pragma unroll
        for (int mi = 0; mi < 2; mi++) {
            #pragma unroll
            for (int half = 0; half < 2; half++) {
                int r = (wm << 5) + (mi << 4) + (half << 3) + g;
                #pragma unroll
                for (int ni = 0; ni < 8; ni++) {
                    int c = (nh << 7) + (wn << 6) + (ni << 3) + (t4 << 1);
                    int cc = c >> 5, q = (c & 31) >> 2, e = c & 3;
                    *(float2*)&fs[Soff + (cc << 12) + (r << 5) + ((q ^ (r & 7)) << 2) + e] =
                        make_float2(acc1[nh][mi][ni][half * 2], acc1[nh][mi][ni][half * 2 + 1]);
                }
            }
        }
    }
    // stats: per (row, nh, wn) partial
    #pragma unroll
    for (int nh = 0; nh < 2; nh++)
        #pragma unroll
        for (int mi = 0; mi < 2; mi++)
            #pragma unroll
            for (int half = 0; half < 2; half++) {
                float m = -1e30f;
                #pragma unroll
                for (int ni = 0; ni < 8; ni++)
                    m = fmaxf(m, fmaxf(acc1[nh][mi][ni][half * 2], acc1[nh][mi][ni][half * 2 + 1]));
                m = fmaxf(m, __shfl_xor_sync(0xffffffffu, m, 1));
                m = fmaxf(m, __shfl_xor_sync(0xffffffffu, m, 2));
                float s = 0.f;
                #pragma unroll
                for (int ni = 0; ni < 8; ni++)
                    s += __expf(acc1[nh][mi][ni][half * 2] - m) + __expf(acc1[nh][mi][ni][half * 2 + 1] - m);
                s += __shfl_xor_sync(0xffffffffu, s, 1);
                s += __shfl_xor_sync(0xffffffffu, s, 2);
                if (t4 == 0) {
                    int rl = (wm << 5) + (mi << 4) + (half << 3) + g;
                    redm[rl * 4 + nh * 2 + wn] = m;
                    reds[rl * 4 + nh * 2 + wn] = s;
                }
            }
    __syncthreads();

    // ---- combine stats (threads 0..127) ----
    if (tid < 128) {
        float m0 = redm[tid * 4], m1 = redm[tid * 4 + 1];
        float m2 = redm[tid * 4 + 2], m3 = redm[tid * 4 + 3];
        float m = fmaxf(fmaxf(m0, m1), fmaxf(m2, m3));
        float s = reds[tid * 4] * __expf(m0 - m) + reds[tid * 4 + 1] * __expf(m1 - m)
                + reds[tid * 4 + 2] * __expf(m2 - m) + reds[tid * 4 + 3] * __expf(m3 - m);
        stm[tid] = m;
        sti[tid] = 1.f / s;
    }
    __syncthreads();

    // ---- stage ZAV into R1 (n*259 + k) + exp-transform Ssm in place ----
    #pragma unroll
    for (int it = 0; it < 64; it++) {
        int idx = (it << 8) + tid;
        int k = idx >> 6, n = idx & 63;
        fs[R1off + n * 259 + k] = ZAV[(long long)k * 64 + n];
    }
    #pragma unroll
    for (int it = 0; it < 128; it++) {
        int i = (it << 8) + tid;
        int r = (i & 4095) >> 5;
        float v = fs[Soff + i];
        fs[Soff + i] = __expf(v - stm[r]) * sti[r];
    }
    __syncthreads();

    // ---- phase 2: OH = P @ ZAV (128 x 64, K=256) ----
    float acc2[8][4];
    #pragma unroll
    for (int ni = 0; ni < 8; ni++)
        #pragma unroll
        for (int q = 0; q < 4; q++) acc2[ni][q] = 0.f;

    #pragma unroll
    for (int cc = 0; cc < 8; cc++) {
        #pragma unroll
        for (int kt = 0; kt < 4; kt++) {
            unsigned a[4];
            {
                int row = (wid << 4) + ((j & 1) << 3) + rho;
                int quad = (kt << 1) + (j >> 1);
                LDMX4(a, sbase + ((Soff + (cc << 12) + (row << 5) + ((quad ^ (row & 7)) << 2)) << 2));
            }
            #pragma unroll
            for (int ni = 0; ni < 8; ni++) {
                int n = (ni << 3) + g;
                unsigned b[2];
                b[0] = __float_as_uint(fs[R1off + n * 259 + (cc << 5) + (kt << 3) + t4]);
                b[1] = __float_as_uint(fs[R1off + n * 259 + (cc << 5) + (kt << 3) + t4 + 4]);
                MMA_TF32(acc2[ni], a, b);
            }
        }
    }

    #pragma unroll
    for (int half = 0; half < 2; half++) {
        int r = row0 + (wid << 4) + (half << 3) + g;
        #pragma unroll
        for (int ni = 0; ni < 8; ni++) {
            int c = (ni << 3) + (t4 << 1);
            *(float2*)(OH + (long long)r * 64 + c) =
                make_float2(acc2[ni][half * 2], acc2[ni][half * 2 + 1]);
        }
    }
}

// ===================== pinv: persistent chain kernel ========================
__device__ __forceinline__ void gbar(unsigned target) {
    __syncthreads();
    if (threadIdx.x == 0) {
        __threadfence();
        atomicAdd(&g_bar, 1u);
        while (*(volatile unsigned*)&g_bar < target) {}
        __threadfence();
    }
    __syncthreads();
}

__device__ void pg_tile(const float* __restrict__ Ag, const float* __restrict__ Bg,
                        float* __restrict__ Cg, float alpha, int bmode, float bd,
                        float* ps)
{
    int bid = blockIdx.x;
    int tid = threadIdx.x;
    int lane = tid & 31, wid = tid >> 5;
    int wm = wid & 3, wn = wid >> 2;
    int col0 = (bid & 1) << 7;
    int row0 = ((bid >> 1) & 3) << 6;
    long long zo = (long long)(bid >> 3) << 16;
    Ag += zo; Bg += zo; Cg += zo;

    float acc[8][4];
    #pragma unroll
    for (int ni = 0; ni < 8; ni++)
        #pragma unroll
        for (int q = 0; q < 4; q++) acc[ni][q] = 0.f;

    int ar = tid >> 2, aq = tid & 3;
    int bn = tid & 127, bkh = tid >> 7;

    float4 pa;
    float pbv[8];

    auto fetch = [&](int k0) {
        pa = *(const float4*)(Ag + ((long long)(row0 + ar) << 8) + k0 + (aq << 2));
        #pragma unroll
        for (int j = 0; j < 8; j++) {
            int gk = k0 + (bkh << 3) + j;
            int gn = col0 + bn;
            float v = Bg[((long long)gk << 8) + gn];
            if (bmode) v = (gk == gn ? bd : 0.f) - v;
            pbv[j] = v;
        }
    };

    auto stash = [&](int s) {
        float* Sb = ps + s * 7680;
        float4 h, l;
        h.x = tf32f(pa.x); h.y = tf32f(pa.y); h.z = tf32f(pa.z); h.w = tf32f(pa.w);
        l.x = tf32f(pa.x - h.x); l.y = tf32f(pa.y - h.y);
        l.z = tf32f(pa.z - h.z); l.w = tf32f(pa.w - h.w);
        *(float4*)&Sb[ar * 20 + (aq << 2)] = h;
        *(float4*)&Sb[1280 + ar * 20 + (aq << 2)] = l;
        float4 bh0, bh1, bl0, bl1;
        bh0.x = tf32f(pbv[0]); bh0.y = tf32f(pbv[1]); bh0.z = tf32f(pbv[2]); bh0.w = tf32f(pbv[3]);
        bh1.x = tf32f(pbv[4]); bh1.y = tf32f(pbv[5]); bh1.z = tf32f(pbv[6]); bh1.w = tf32f(pbv[7]);
        bl0.x = tf32f(pbv[0] - bh0.x); bl0.y = tf32f(pbv[1] - bh0.y);
        bl0.z = tf32f(pbv[2] - bh0.z); bl0.w = tf32f(pbv[3] - bh0.w);
        bl1.x = tf32f(pbv[4] - bh1.x); bl1.y = tf32f(pbv[5] - bh1.y);
        bl1.z = tf32f(pbv[6] - bh1.z); bl1.w = tf32f(pbv[7] - bh1.w);
        *(float4*)&Sb[2560 + bn * 20 + (bkh << 3)] = bh0;
        *(float4*)&Sb[2560 + bn * 20 + (bkh << 3) + 4] = bh1;
        *(float4*)&Sb[5120 + bn * 20 + (bkh << 3)] = bl0;
        *(float4*)&Sb[5120 + bn * 20 + (bkh << 3) + 4] = bl1;
    };

    auto compute = [&](int s) {
        const float* Sb = ps + s * 7680;
        int g = lane >> 2, t = lane & 3;
        #pragma unroll
        for (int kt = 0; kt < 2; kt++) {
            int kb = kt << 3;
            int m = (wm << 4) + g;
            unsigned ah[4], al[4];
            ah[0] = __float_as_uint(Sb[m * 20 + kb + t]);
            ah[1] = __float_as_uint(Sb[(m + 8) * 20 + kb + t]);
            ah[2] = __float_as_uint(Sb[m * 20 + kb + t + 4]);
            ah[3] = __float_as_uint(Sb[(m + 8) * 20 + kb + t + 4]);
            al[0] = __float_as_uint(Sb[1280 + m * 20 + kb + t]);
            al[1] = __float_as_uint(Sb[1280 + (m + 8) * 20 + kb + t]);
            al[2] = __float_as_uint(Sb[1280 + m * 20 + kb + t + 4]);
            al[3] = __float_as_uint(Sb[1280 + (m + 8) * 20 + kb + t + 4]);
            #pragma unroll
            for (int ni = 0; ni < 8; ni++) {
                int n = (wn << 6) + (ni << 3) + g;
                unsigned bh[2], bl[2];
                bh[0] = __float_as_uint(Sb[2560 + n * 20 + kb + t]);
                bh[1] = __float_as_uint(Sb[2560 + n * 20 + kb + t + 4]);
                bl[0] = __float_as_uint(Sb[5120 + n * 20 + kb + t]);
                bl[1] = __float_as_uint(Sb[5120 + n * 20 + kb + t + 4]);
                MMA_TF32(acc[ni], ah, bh);
                MMA_TF32(acc[ni], ah, bl);
                MMA_TF32(acc[ni], al, bh);
            }
        }
    };

    fetch(0);
    for (int ch = 0; ch < 16; ch++) {
        stash(ch & 1);
        __syncthreads();
        if (ch < 15) fetch((ch + 1) << 4);
        compute(ch & 1);
        __syncthreads();
    }

    int g = lane >> 2, t = lane & 3;
    #pragma unroll
    for (int half = 0; half < 2; half++) {
        int r = row0 + (wm << 4) + (half << 3) + g;
        #pragma unroll
        for (int ni = 0; ni < 8; ni++) {
            int c = col0 + (wn << 6) + (ni << 3) + (t << 1);
            *(float2*)(Cg + ((long long)r << 8) + c) =
                make_float2(acc[ni][half * 2] * alpha, acc[ni][half * 2 + 1] * alpha);
        }
    }
}

__global__ void __launch_bounds__(256) pinvchain_k()
{
    extern __shared__ float ps[];
    int bid = blockIdx.x;
    int tid = threadIdx.x;

    if (bid < 16) {
        const float* S = g_S2 + ((long long)bid << 16);
        float rs = 0.f, cs = 0.f;
        for (int j = 0; j < 256; j++) {
            rs += S[(tid << 8) + j];
            cs += S[(j << 8) + tid];
        }
        float rm = blockReduce(rs, true);
        float cm = blockReduce(cs, true);
        if (tid == 0) {
            atomicMax(&g_scale[0], __float_as_uint(rm));
            atomicMax(&g_scale[1], __float_as_uint(cm));
        }
    }
    gbar(128);

    {
        float inv = 1.0f / (__uint_as_float(g_scale[0]) * __uint_as_float(g_scale[1]));
        #pragma unroll
        for (int e = 0; e < 32; e++) {
            int idx = (bid << 13) + (e << 8) + tid;
            int z = idx >> 16, r = idx & 65535;
            int i = r >> 8, j = r & 255;
            g_Zb[((long long)z << 16) + (i << 8) + j] =
                g_S2[((long long)z << 16) + (j << 8) + i] * inv;
        }
    }
    gbar(256);

    unsigned t = 256;
    for (int it = 0; it < 6; it++) {
        float* Zi = (it & 1) ? g_Z2b : g_Zb;
        float* Zo = (it & 1) ? g_Zb : g_Z2b;
        pg_tile(g_S2, Zi, g_Pb, 1.f, 0, 0.f, ps);  t += 128; gbar(t);
        pg_tile(g_Pb, g_Pb, g_T2b, 1.f, 1, 7.f, ps);  t += 128; gbar(t);
        pg_tile(g_Pb, g_T2b, g_Tb, 1.f, 1, 15.f, ps);  t += 128; gbar(t);
        pg_tile(Zi, g_Tb, Zo, 0.25f, 1, 13.f, ps);  t += 128; gbar(t);
    }
}

__global__ void reset_k() { g_scale[0] = 0u; g_scale[1] = 0u; g_bar = 0u; }

// ------------------------- layernorm (rows of 512) --------------------------
__global__ void __launch_bounds__(256) ln_k(const float* __restrict__ X, float* __restrict__ Y,
                                            const float* __restrict__ g, const float* __restrict__ b)
{
    long long row = blockIdx.x;
    const float* x = X + row * DIMM;
    float* y = Y + row * DIMM;
    int t = threadIdx.x;
    float v0 = x[t], v1 = x[t + 256];
    float mu  = blockReduce(v0 + v1, false) * (1.f / 512.f);
    float d0 = v0 - mu, d1 = v1 - mu;
    float var = blockReduce(d0 * d0 + d1 * d1, false) * (1.f / 512.f);
    float inv = rsqrtf(var + 1e-5f);
    y[t]       = d0 * inv * g[t]       + b[t];
    y[t + 256] = d1 * inv * g[t + 256] + b[t + 256];
}

// ------------------------- softmax (S2 only) --------------------------------
__global__ void __launch_bounds__(256) softmax256_k(float* __restrict__ S)
{
    long long row = ((long long)blockIdx.x << 3) + (threadIdx.x >> 5);
    int lane = threadIdx.x & 31;
    float* s = S + (row << 8);
    float4 va = *(float4*)(s + (lane << 3));
    float4 vb = *(float4*)(s + (lane << 3) + 4);
    float m = fmaxf(fmaxf(fmaxf(va.x, va.y), fmaxf(va.z, va.w)),
                    fmaxf(fmaxf(vb.x, vb.y), fmaxf(vb.z, vb.w)));
    #pragma unroll
    for (int o = 16; o > 0; o >>= 1) m = fmaxf(m, __shfl_xor_sync(0xffffffffu, m, o));
    va.x = __expf(va.x - m); va.y = __expf(va.y - m); va.z = __expf(va.z - m); va.w = __expf(va.w - m);
    vb.x = __expf(vb.x - m); vb.y = __expf(vb.y - m); vb.z = __expf(vb.z - m); vb.w = __expf(vb.w - m);
    float sum = va.x + va.y + va.z + va.w + vb.x + vb.y + vb.z + vb.w;
    #pragma unroll
    for (int o = 16; o > 0; o >>= 1) sum += __shfl_xor_sync(0xffffffffu, sum, o);
    float inv = 1.f / sum;
    va.x *= inv; va.y *= inv; va.z *= inv; va.w *= inv;
    vb.x *= inv; vb.y *= inv; vb.z *= inv; vb.w *= inv;
    *(float4*)(s + (lane << 3)) = va;
    *(float4*)(s + (lane << 3) + 4) = vb;
}

// ------------------------- landmarks ----------------------------------------
__global__ void __launch_bounds__(64) landmark_k()
{
    int zz = blockIdx.x;
    int mi = zz & 255, bh = zz >> 8;
    int b = bh >> 3, h = bh & 7;
    int d = threadIdx.x;
    const float* base = g_QKV + (long long)(b * NF + mi * 32) * QD + h * 64 + d;
    float sq = 0.f, sk = 0.f;
    #pragma unroll 8
    for (int il = 0; il < 32; il++) {
        sq += base[(long long)il * QD];
        sk += base[(long long)il * QD + 512];
    }
    long long o = ((long long)bh * LM + mi) * DH + d;
    g_QL[o] = sq * (1.f / 32.f);
    g_KL[o] = sk * (1.f / 32.f);
}

// ------------------------- split-K reduce for AV ----------------------------
__global__ void __launch_bounds__(256) avreduce_k()
{
    int idx = blockIdx.x * 256 + threadIdx.x;
    int bh = idx >> 14;
    int r  = idx & 16383;
    const float* p = g_AVp + ((long long)bh << 17);
    float s = 0.f;
    #pragma unroll
    for (int k = 0; k < KSPL; k++) s += p[(k << 14) + r];
    g_AV[idx] = s;
}

// ------------------------- depthwise conv residual --------------------------
__global__ void __launch_bounds__(256) conv_k(const float* __restrict__ cw)
{
    __shared__ float sv[160 * 64];
    __shared__ float sw[KER];
    int tile = blockIdx.x;
    int bh = blockIdx.y;
    int b = bh >> 3, h = bh & 7;
    int n0 = tile * 128;
    int t = threadIdx.x;
    if (t < KER) sw[t] = cw[h * KER + t];
    for (int idx = t; idx < 160 * 64; idx += 256) {
        int r = idx >> 6, d = idx & 63;
        int nn = n0 - 16 + r;
        float v = 0.f;
        if (nn >= 0 && nn < NF) v = g_QKV[(long long)(b * NF + nn) * QD + 1024 + h * 64 + d];
        sv[idx] = v;
    }
    __syncthreads();
    int d = t & 63, r0 = t >> 6;
    for (int rr = r0; rr < 128; rr += 4) {
        float a = 0.f;
        #pragma unroll
        for (int k = 0; k < KER; k++) a += sv[(rr + k) * 64 + d] * sw[k];
        long long o = ((long long)bh * NF + n0 + rr) * DH + d;
        g_OH[o] += a;
    }
}

// ------------------------- final LN + head ----------------------------------
__global__ void __launch_bounds__(256) final_k(const float* __restrict__ fg, const float* __restrict__ fb,
                                               const float* __restrict__ w2, const float* __restrict__ b2,
                                               float* __restrict__ out)
{
    int b = blockIdx.x;
    const float* x = g_X + (long long)b * NF * DIMM;
    int t = threadIdx.x;
    float v0 = x[t], v1 = x[t + 256];
    float mu  = blockReduce(v0 + v1, false) * (1.f / 512.f);
    float d0 = v0 - mu, d1 = v1 - mu;
    float var = blockReduce(d0 * d0 + d1 * d1, false) * (1.f / 512.f);
    float inv = rsqrtf(var + 1e-5f);
    float n0 = d0 * inv * fg[t]       + fb[t];
    float n1 = d1 * inv * fg[t + 256] + fb[t + 256];
    float p0 = n0 * w2[2 * t]     + n1 * w2[2 * (t + 256)];
    float p1 = n0 * w2[2 * t + 1] + n1 * w2[2 * (t + 256) + 1];
    p0 = blockReduce(p0, false);
    p1 = blockReduce(p1, false);
    if (t == 0) {
        out[b * 2 + 0] = p0 + b2[0];
        out[b * 2 + 1] = p1 + b2[1];
    }
}

// ------------------------- host orchestration -------------------------------
static inline void mgemm2(int M, int N, int K,
                          const float* A, int lda, long long sA1, long long sA2, int amode,
                          const float* BT, int ldbt, long long sBT1, long long sBT2,
                          float* C, int ldc, long long sC1, long long sC2,
                          int batch, int ep, const float* bias,
                          float2* RSp = nullptr, long long rsp1 = 0, long long rsp2 = 0)
{
    dim3 g(N >> 7, (M + 127) >> 7, batch);
    if (RSp) {
        cudaFuncSetAttribute(mgemm2_k<1>, cudaFuncAttributeMaxDynamicSharedMemorySize, 98304);
        mgemm2_k<1><<<g, 256, 98304>>>(M, K, A, lda, sA1, sA2, amode, BT, ldbt, sBT1, sBT2,
                                       C, ldc, sC1, sC2, ep, bias, RSp, rsp1, rsp2);
    } else {
        cudaFuncSetAttribute(mgemm2_k<0>, cudaFuncAttributeMaxDynamicSharedMemorySize, 98304);
        mgemm2_k<0><<<g, 256, 98304>>>(M, K, A, lda, sA1, sA2, amode, BT, ldbt, sBT1, sBT2,
                                       C, ldc, sC1, sC2, ep, bias, nullptr, 0, 0);
    }
}

static inline void agemm(int M, int K,
                         const float* A, int lda, long long sA1, long long sA2, long long sA3,
                         const float* B, int ldb, long long sB1, long long sB2, long long sB3,
                         float* C, long long sC1, long long sC2, long long sC3,
                         int SPLIT, int batchZ, float alpha,
                         const float2* rsA, long long rs1, long long rs2, int aexp)
{
    cudaFuncSetAttribute(agemm_k, cudaFuncAttributeMaxDynamicSharedMemorySize, 49664);
    dim3 g(1, M >> 7, batchZ);
    agemm_k<<<g, 256, 49664>>>(M, K, A, lda, sA1, sA2, sA3, B, ldb, sB1, sB2, sB3,
                               C, sC1, sC2, sC3, SPLIT, alpha, rsA, rs1, rs2, aexp);
}

extern "C" void kernel_launch(void* const* d_in, const int* in_sizes, int n_in,
                              void* d_out, int out_size)
{
    const float* h_in  = (const float*)d_in[0];
    const float* w1    = (const float*)d_in[1];
    const float* b1    = (const float*)d_in[2];
    const float* clst  = (const float*)d_in[3];
    const float* ln_g  = (const float*)d_in[4];
    const float* ln_b  = (const float*)d_in[5];
    const float* wqkv  = (const float*)d_in[6];
    const float* wout  = (const float*)d_in[7];
    const float* bout  = (const float*)d_in[8];
    const float* cw    = (const float*)d_in[9];
    const float* fg    = (const float*)d_in[10];
    const float* fb    = (const float*)d_in[11];
    const float* w2    = (const float*)d_in[12];
    const float* b2    = (const float*)d_in[13];
    float* out = (float*)d_out;

    float *X, *XN, *QKV, *QL, *KL, *S3, *S2p, *Z, *AV, *AVp, *ZAV, *OH, *WT;
    float2 *RS3, *RSp;
    cudaGetSymbolAddress((void**)&X,   g_X);
    cudaGetSymbolAddress((void**)&XN,  g_XN);
    cudaGetSymbolAddress((void**)&QKV, g_QKV);
    cudaGetSymbolAddress((void**)&QL,  g_QL);
    cudaGetSymbolAddress((void**)&KL,  g_KL);
    cudaGetSymbolAddress((void**)&S3,  g_S3);
    cudaGetSymbolAddress((void**)&S2p, g_S2);
    cudaGetSymbolAddress((void**)&Z,   g_Zb);
    cudaGetSymbolAddress((void**)&AV,  g_AV);
    cudaGetSymbolAddress((void**)&AVp, g_AVp);
    cudaGetSymbolAddress((void**)&ZAV, g_ZAV);
    cudaGetSymbolAddress((void**)&OH,  g_OH);
    cudaGetSymbolAddress((void**)&WT,  g_WT);
    cudaGetSymbolAddress((void**)&RS3, g_RS3);
    cudaGetSymbolAddress((void**)&RSp, g_RSp);

    const long long SQb = (long long)NF * QD;
    const long long S2s = (long long)LM * LM;
    const long long S1s = (long long)NF * LM;
    const long long AVs = (long long)LM * DH;

    cudaFuncSetAttribute(pinvchain_k, cudaFuncAttributeMaxDynamicSharedMemorySize, 61440);
    cudaFuncSetAttribute(fOH_k, cudaFuncAttributeMaxDynamicSharedMemorySize, 229376);

    // #1: all weight transposes + cls fill
    transAll_k<<<2564, 256>>>(w1, wqkv, wout, clst);

    // #2: input projection
    mgemm2(NB * 8191, DIMM, 1024, h_in, 1024, 0, 0, 0, WT + OW1, 1024, 0, 0,
           X, DIMM, 0, 0, 1, EP_RELU_REMAP, b1);

    for (int L = 0; L < 2; L++) {
        // #3 (L=0): layernorm
        ln_k<<<TOT, 256>>>(X, XN, ln_g + L * DIMM, ln_b + L * DIMM);

        // #4 (L=0): qkv GEMM  <-- ncu capture slot
        mgemm2(TOT, QD, DIMM, XN, DIMM, 0, 0, 0, WT + OQKV(L), DIMM, 0, 0,
               QKV, QD, 0, 0, 1, EP_SCALEQ, nullptr);

        landmark_k<<<NBH * LM, 64>>>();

        // sim2 = QL @ KL^T, softmax
        mgemm2(LM, LM, DH, QL, DH, 8 * AVs, AVs, 0, KL, DH, 8 * AVs, AVs,
               S2p, LM, 8 * S2s, S2s, NBH, EP_NONE, nullptr);
        softmax256_k<<<NBH * LM / 8, 256>>>(S2p);

        // Moore-Penrose pinv of S2 -> Z : persistent chain
        reset_k<<<1, 1>>>();
        pinvchain_k<<<128, 256, 61440>>>();

        // sim3 = QL @ K^T (raw) with fused per-tile softmax stats (64/row)
        mgemm2(LM, NF, DH, QL, DH, 8 * AVs, AVs, 0, QKV + 512, QD, SQb, 64,
               S3, NF, 8 * S1s, S1s, NBH, EP_NONE, nullptr,
               RSp, 8LL * LM * 64, (long long)LM * 64);
        combine_k<<<NBH * LM / 8, 256>>>(RSp, RS3, 64);

        // AV = softmax(sim3) @ V  (tensor, exp fused, split-K by 8)
        agemm(LM, NF / KSPL,
              S3, NF, 8 * S1s, S1s, 1024,
              QKV + 1024, QD, SQb, 64, 1024LL * QD,
              AVp, 64 * AVs, 8 * AVs, AVs,
              KSPL, NBH * KSPL, 1.f, RS3, 8 * LM, LM, 1);
        avreduce_k<<<1024, 256>>>();

        // ZAV = Z @ AV  (tensor)
        agemm(LM, LM,
              Z, LM, 8 * S2s, S2s, 0,
              AV, DH, 8 * AVs, AVs, 0,
              ZAV, 8 * AVs, AVs, 0,
              1, NBH, 1.f, RS3, 0, 0, 0);

        // OH = softmax(Q @ KL^T) @ ZAV  (fully fused, exact softmax)
        fOH_k<<<dim3(NF / 128, NBH), 256, 229376>>>(QKV, KL, ZAV, OH);

        // OH += depthwise conv residual of V
        { dim3 g(NF / 128, NBH); conv_k<<<g, 256>>>(cw + L * NH * KER); }

        // X += OH(head-layout) @ Wout + bout
        mgemm2(TOT, DIMM, DIMM, OH, 0, 0, 0, 1, WT + OOUT(L), DIMM, 0, 0,
               X, DIMM, 0, 0, 1, EP_ADDBIAS, bout + L * DIMM);
    }

    final_k<<<NB, 256>>>(fg, fb, w2, b2, out);
}

// round 16
// speedup vs baseline: 2.9593x; 1.0436x over previous
#include <cuda_runtime.h>

#define NB   2
#define NF   8192
#define DIMM 512
#define NH   8
#define DH   64
#define LM   256
#define QD   1536
#define TOT  (NB*NF)    // 16384
#define NBH  (NB*NH)    // 16
#define KER  33
#define KSPL 8

// ------------------------- scratch (device globals, no allocs) -------------
__device__ float g_X  [TOT*DIMM];
__device__ float g_XN [TOT*DIMM];
__device__ float g_QKV[TOT*QD];
__device__ float g_QL [NBH*LM*DH];
__device__ float g_KL [NBH*LM*DH];
__device__ float g_S2 [NBH*LM*LM];
__device__ float g_Zb [NBH*LM*LM];
__device__ float g_Z2b[NBH*LM*LM];
__device__ float g_Pb [NBH*LM*LM];
__device__ float g_Tb [NBH*LM*LM];
__device__ float g_T2b[NBH*LM*LM];
__device__ float g_AV [NBH*LM*DH];
__device__ float g_AVp[NBH*KSPL*LM*DH];
__device__ float g_ZAV[NBH*LM*DH];
__device__ float g_OH [NBH*NF*DH];
__device__ float g_WT [2621440];
__device__ float2 g_RS3[NBH*LM];
__device__ float2 g_RSp[NBH*LM*64];
__device__ unsigned int g_scale[2];
__device__ unsigned int g_bar;

enum { EP_NONE = 0, EP_RELU_REMAP = 1, EP_SCALEQ = 2, EP_ADDBIAS = 3 };

#define OW1   0
#define OQKV(L) (524288 + (L) * 786432)
#define OOUT(L) (2097152 + (L) * 262144)

__device__ __forceinline__ unsigned f2tf32(float f) {
    unsigned r;
    asm("cvt.rna.tf32.f32 %0, %1;" : "=r"(r) : "f"(f));
    return r;
}
__device__ __forceinline__ float tf32f(float f) {
    return __uint_as_float(f2tf32(f));
}

#define MMA_TF32(d, a, b) \
    asm volatile("mma.sync.aligned.m16n8k8.row.col.f32.tf32.tf32.f32 " \
        "{%0,%1,%2,%3}, {%4,%5,%6,%7}, {%8,%9}, {%0,%1,%2,%3};" \
        : "+f"((d)[0]), "+f"((d)[1]), "+f"((d)[2]), "+f"((d)[3]) \
        : "r"((a)[0]), "r"((a)[1]), "r"((a)[2]), "r"((a)[3]), \
          "r"((b)[0]), "r"((b)[1]))

#define LDMX4(v, ad) \
    asm volatile("ldmatrix.sync.aligned.m8n8.x4.shared.b16 {%0,%1,%2,%3}, [%4];" \
        : "=r"((v)[0]), "=r"((v)[1]), "=r"((v)[2]), "=r"((v)[3]) : "r"(ad))

// ------------------------- reductions --------------------------------------
__device__ __forceinline__ float blockReduce(float v, bool domax) {
    __shared__ float sh[32];
    __syncthreads();
    #pragma unroll
    for (int o = 16; o > 0; o >>= 1) {
        float w = __shfl_down_sync(0xffffffffu, v, o);
        v = domax ? fmaxf(v, w) : v + w;
    }
    int lane = threadIdx.x & 31, wid = threadIdx.x >> 5;
    if (lane == 0) sh[wid] = v;
    __syncthreads();
    int nw = (blockDim.x + 31) >> 5;
    if (wid == 0) {
        v = (lane < nw) ? sh[lane] : (domax ? -1e30f : 0.f);
        #pragma unroll
        for (int o = 16; o > 0; o >>= 1) {
            float w = __shfl_down_sync(0xffffffffu, v, o);
            v = domax ? fmaxf(v, w) : v + w;
        }
        if (lane == 0) sh[0] = v;
    }
    __syncthreads();
    return sh[0];
}

// ------------------- fused transposes + cls (ONE launch) --------------------
__device__ __forceinline__ void doTrans(const float* __restrict__ src,
                                        float* __restrict__ dst,
                                        int K, int N, int kt, int nt)
{
    __shared__ float t[32][33];
    int kb = kt << 5, nb = nt << 5;
    int x = threadIdx.x & 31, y = threadIdx.x >> 5;
    #pragma unroll
    for (int i = 0; i < 32; i += 8)
        t[y + i][x] = src[(long long)(kb + y + i) * N + nb + x];
    __syncthreads();
    #pragma unroll
    for (int i = 0; i < 32; i += 8)
        dst[(long long)(nb + y + i) * K + kb + x] = t[x][y + i];
}

__global__ void __launch_bounds__(256) transAll_k(
    const float* __restrict__ w1, const float* __restrict__ wqkv,
    const float* __restrict__ wout, const float* __restrict__ clst)
{
    int b = blockIdx.x;
    if (b < 512) {
        doTrans(w1, g_WT + OW1, 1024, DIMM, b & 31, b >> 5);
    } else if (b < 2048) {
        int L = (b - 512) / 768, bb = (b - 512) % 768;
        doTrans(wqkv + (long long)L * DIMM * QD, g_WT + OQKV(L), DIMM, QD, bb & 15, bb >> 4);
    } else if (b < 2560) {
        int L = (b - 2048) / 256, bb = (b - 2048) % 256;
        doTrans(wout + (long long)L * DIMM * DIMM, g_WT + OOUT(L), DIMM, DIMM, bb & 15, bb >> 4);
    } else {
        int idx = (b - 2560) * 256 + threadIdx.x;
        int bb = idx >> 9, c = idx & 511;
        g_X[(long long)bb * NF * DIMM + c] = clst[c];
    }
}

// ======= mgemm2: cp.async + ldmatrix tf32, 128x128, 3-stage, 2 CTA/SM =======
__device__ __forceinline__ void cp16(unsigned dst, const void* src, int nbytes) {
    asm volatile("cp.async.cg.shared.global [%0], [%1], 16, %2;"
                 :: "r"(dst), "l"(src), "r"(nbytes) : "memory");
}

template<int STAT>
__global__ void __launch_bounds__(256, 2) mgemm2_k(
    int M, int K,
    const float* __restrict__ A, int lda, long long sA1, long long sA2, int amode,
    const float* __restrict__ BT, int ldbt, long long sBT1, long long sBT2,
    float* __restrict__ C, int ldc, long long sC1, long long sC2,
    int ep, const float* __restrict__ bias,
    float2* __restrict__ RSp, long long rsp1, long long rsp2)
{
    extern __shared__ float smem[];   // 3 stages x 32KB = 96KB
    int tid = threadIdx.x;
    int lane = tid & 31, wid = tid >> 5;
    int wm = wid & 3, wn = wid >> 2;
    int row0 = blockIdx.y << 7, col0 = blockIdx.x << 7;
    int z = blockIdx.z;
    A  += (long long)(z >> 3) * sA1 + (long long)(z & 7) * sA2;
    BT += (long long)(z >> 3) * sBT1 + (long long)(z & 7) * sBT2;
    C  += (long long)(z >> 3) * sC1 + (long long)(z & 7) * sC2;
    if (STAT) RSp += (long long)(z >> 3) * rsp1 + (long long)(z & 7) * rsp2;

    unsigned sbase;
    asm("{ .reg .u64 t; cvta.to.shared.u64 t, %1; cvt.u32.u64 %0, t; }"
        : "=r"(sbase) : "l"(smem));

    float acc[2][8][4];
    #pragma unroll
    for (int mi = 0; mi < 2; mi++)
        #pragma unroll
        for (int ni = 0; ni < 8; ni++)
            #pragma unroll
            for (int q = 0; q < 4; q++) acc[mi][ni][q] = 0.f;

    auto fill = [&](int s, int k0) {
        unsigned Ab = sbase + s * 32768u;
        unsigned Bb = Ab + 16384u;
        #pragma unroll
        for (int it = 0; it < 4; it++) {
            int idx = (it << 8) + tid;
            int q = idx & 7, r = idx >> 3;
            int gr = row0 + r;
            const float* src;
            int nb = 16;
            if (amode == 0) {
                int gra = gr < M ? gr : (M - 1);
                if (gr >= M) nb = 0;
                src = A + (long long)gra * lda + k0 + (q << 2);
            } else {
                int k = k0 + (q << 2);
                int h = k >> 6, d = k & 63;
                src = A + ((((long long)(gr >> 13) << 3) + h) * 8192 + (gr & 8191)) * 64 + d;
            }
            unsigned dst = Ab + (((r << 5) + ((q ^ (r & 7)) << 2)) << 2);
            cp16(dst, src, nb);
        }
        #pragma unroll
        for (int it = 0; it < 4; it++) {
            int idx = (it << 8) + tid;
            int q = idx & 7, n = idx >> 3;
            const float* src = BT + (long long)(col0 + n) * ldbt + k0 + (q << 2);
            unsigned dst = Bb + (((n << 5) + ((q ^ (n & 7)) << 2)) << 2);
            cp16(dst, src, 16);
        }
        asm volatile("cp.async.commit_group;" ::: "memory");
    };

    auto compute = [&](int s) {
        unsigned Ab = sbase + s * 32768u;
        unsigned Bb = Ab + 16384u;
        int j = lane >> 3, rho = lane & 7;
        #pragma unroll
        for (int kt = 0; kt < 4; kt++) {
            unsigned a[2][4];
            #pragma unroll
            for (int mi = 0; mi < 2; mi++) {
                int row = (wm << 5) + (mi << 4) + ((j & 1) << 3) + rho;
                int quad = (kt << 1) + (j >> 1);
                unsigned ad = Ab + (((row << 5) + ((quad ^ (row & 7)) << 2)) << 2);
                LDMX4(a[mi], ad);
            }
            unsigned b[8][2];
            #pragma unroll
            for (int np = 0; np < 4; np++) {
                int row = (((wn << 3) + (np << 1) + (j >> 1)) << 3) + rho;
                int quad = (kt << 1) + (j & 1);
                unsigned bd = Bb + (((row << 5) + ((quad ^ (row & 7)) << 2)) << 2);
                unsigned v[4];
                LDMX4(v, bd);
                b[np * 2][0] = v[0]; b[np * 2][1] = v[1];
                b[np * 2 + 1][0] = v[2]; b[np * 2 + 1][1] = v[3];
            }
            #pragma unroll
            for (int mi = 0; mi < 2; mi++)
                #pragma unroll
                for (int ni = 0; ni < 8; ni++)
                    MMA_TF32(acc[mi][ni], a[mi], b[ni]);
        }
    };

    int nch = K >> 5;
    fill(0, 0);
    if (nch > 1) fill(1, 32);
    for (int ch = 0; ch < nch; ch++) {
        if (ch + 1 < nch)
            asm volatile("cp.async.wait_group 1;" ::: "memory");
        else
            asm volatile("cp.async.wait_group 0;" ::: "memory");
        __syncthreads();
        if (ch + 2 < nch) fill((ch + 2) % 3, (ch + 2) << 5);
        compute(ch % 3);
    }

    int rb = row0 + (wm << 5) + (lane >> 2);
    int cb = col0 + (wn << 6) + ((lane & 3) << 1);
    #pragma unroll
    for (int mi = 0; mi < 2; mi++) {
        #pragma unroll
        for (int half = 0; half < 2; half++) {
            int r = rb + (mi << 4) + (half << 3);
            if (r >= M) continue;
            #pragma unroll
            for (int ni = 0; ni < 8; ni++) {
                int c = cb + (ni << 3);
                float v0 = acc[mi][ni][half * 2];
                float v1 = acc[mi][ni][half * 2 + 1];
                if (ep == EP_RELU_REMAP) {
                    long long o = (long long)(r + r / 8191 + 1) * ldc + c;
                    v0 = fmaxf(v0 + bias[c], 0.f);
                    v1 = fmaxf(v1 + bias[c + 1], 0.f);
                    *(float2*)(C + o) = make_float2(v0, v1);
                } else if (ep == EP_SCALEQ) {
                    float sc = (c < 512) ? 0.125f : 1.0f;
                    *(float2*)(C + (long long)r * ldc + c) = make_float2(v0 * sc, v1 * sc);
                } else if (ep == EP_ADDBIAS) {
                    long long o = (long long)r * ldc + c;
                    float2 old = *(float2*)(C + o);
                    *(float2*)(C + o) = make_float2(old.x + v0 + bias[c],
                                                    old.y + v1 + bias[c + 1]);
                } else {
                    *(float2*)(C + (long long)r * ldc + c) = make_float2(v0, v1);
                }
            }
        }
    }

    if (STAT) {
        float* red = smem;
        int g = lane >> 2;
        float rowm[2][2];
        __syncthreads();
        #pragma unroll
        for (int mi = 0; mi < 2; mi++) {
            #pragma unroll
            for (int half = 0; half < 2; half++) {
                float m = -1e30f;
                #pragma unroll
                for (int ni = 0; ni < 8; ni++)
                    m = fmaxf(m, fmaxf(acc[mi][ni][half * 2], acc[mi][ni][half * 2 + 1]));
                m = fmaxf(m, __shfl_xor_sync(0xffffffffu, m, 1));
                m = fmaxf(m, __shfl_xor_sync(0xffffffffu, m, 2));
                if ((lane & 3) == 0) {
                    int rl = (wm << 5) + (mi << 4) + (half << 3) + g;
                    red[rl * 2 + wn] = m;
                }
            }
        }
        __syncthreads();
        #pragma unroll
        for (int mi = 0; mi < 2; mi++) {
            #pragma unroll
            for (int half = 0; half < 2; half++) {
                int rl = (wm << 5) + (mi << 4) + (half << 3) + g;
                rowm[mi][half] = fmaxf(red[rl * 2], red[rl * 2 + 1]);
            }
        }
        __syncthreads();
        #pragma unroll
        for (int mi = 0; mi < 2; mi++) {
            #pragma unroll
            for (int half = 0; half < 2; half++) {
                float m = rowm[mi][half];
                float s = 0.f;
                #pragma unroll
                for (int ni = 0; ni < 8; ni++)
                    s += __expf(acc[mi][ni][half * 2] - m) + __expf(acc[mi][ni][half * 2 + 1] - m);
                s += __shfl_xor_sync(0xffffffffu, s, 1);
                s += __shfl_xor_sync(0xffffffffu, s, 2);
                if ((lane & 3) == 0) {
                    int rl = (wm << 5) + (mi << 4) + (half << 3) + g;
                    red[256 + rl * 2 + wn] = s;
                }
            }
        }
        __syncthreads();
        if (wn == 0 && (lane & 3) == 0) {
            #pragma unroll
            for (int mi = 0; mi < 2; mi++) {
                #pragma unroll
                for (int half = 0; half < 2; half++) {
                    int rl = (wm << 5) + (mi << 4) + (half << 3) + g;
                    int gr = row0 + rl;
                    if (gr < M)
                        RSp[(long long)gr * gridDim.x + blockIdx.x] =
                            make_float2(rowm[mi][half],
                                        red[256 + rl * 2] + red[256 + rl * 2 + 1]);
                }
            }
        }
    }
}

// ===================== agemm: tf32 GEMM, 128xN64 tile (ZAV) =================
__global__ void __launch_bounds__(256, 2) agemm_k(
    int M, int K,
    const float* __restrict__ A, int lda, long long sA1, long long sA2, long long sA3,
    const float* __restrict__ B, int ldb, long long sB1, long long sB2, long long sB3,
    float* __restrict__ C, long long sC1, long long sC2, long long sC3,
    int SPLIT, float alpha,
    const float2* __restrict__ rsA, long long rs1, long long rs2, int aexp)
{
    extern __shared__ unsigned dsm[];
    int z = blockIdx.z;
    int s = z % SPLIT;
    int bh = z / SPLIT;
    int hh = bh & 7, bb = bh >> 3;
    A   += (long long)bb * sA1 + (long long)hh * sA2 + (long long)s * sA3;
    B   += (long long)bb * sB1 + (long long)hh * sB2 + (long long)s * sB3;
    C   += (long long)bb * sC1 + (long long)hh * sC2 + (long long)s * sC3;
    rsA += bb * rs1 + hh * rs2;
    int row0 = blockIdx.y << 7;
    int tid = threadIdx.x, lane = tid & 31, wm = tid >> 5;

    unsigned sbase;
    asm("{ .reg .u64 t; cvta.to.shared.u64 t, %1; cvt.u32.u64 %0, t; }"
        : "=r"(sbase) : "l"(dsm));
    float* Bsm = (float*)(dsm + 8192);

    float acc[8][4];
    #pragma unroll
    for (int ni = 0; ni < 8; ni++)
        #pragma unroll
        for (int q = 0; q < 4; q++) acc[ni][q] = 0.f;

    int a_q = tid & 7, a_r0 = tid >> 3;
    int b_n = tid & 63, b_kh = tid >> 6;

    float4 pa[4];
    float pbv[8];

    auto fetch = [&](int k0) {
        #pragma unroll
        for (int it = 0; it < 4; it++) {
            int r = a_r0 + (it << 5);
            int gr = row0 + r;
            float4 v = *(const float4*)(A + (long long)gr * lda + k0 + (a_q << 2));
            if (aexp) {
                float2 st = rsA[gr];
                v.x = __expf(v.x - st.x) * st.y;
                v.y = __expf(v.y - st.x) * st.y;
                v.z = __expf(v.z - st.x) * st.y;
                v.w = __expf(v.w - st.x) * st.y;
            }
            pa[it] = v;
        }
        #pragma unroll
        for (int j = 0; j < 8; j++) {
            int k = (b_kh << 3) + j;
            pbv[j] = B[(long long)(k0 + k) * ldb + b_n];
        }
    };

    auto stash = [&](int st) {
        unsigned* Ab = dsm + st * 4096;
        #pragma unroll
        for (int it = 0; it < 4; it++) {
            int r = a_r0 + (it << 5);
            uint4 u;
            u.x = f2tf32(pa[it].x); u.y = f2tf32(pa[it].y);
            u.z = f2tf32(pa[it].z); u.w = f2tf32(pa[it].w);
            *(uint4*)&Ab[(r << 5) + ((a_q ^ (r & 7)) << 2)] = u;
        }
        float* Bb = Bsm + st * 2112;
        #pragma unroll
        for (int j = 0; j < 8; j++) {
            int k = (b_kh << 3) + j;
            Bb[b_n * 33 + k] = tf32f(pbv[j]);
        }
    };

    auto compute = [&](int st) {
        unsigned Ab = sbase + st * 16384u;
        const float* Bb = Bsm + st * 2112;
        int j = lane >> 3, rho = lane & 7;
        int g = lane >> 2, t = lane & 3;
        #pragma unroll
        for (int kt = 0; kt < 4; kt++) {
            unsigned a[4];
            {
                int row = (wm << 4) + ((j & 1) << 3) + rho;
                int quad = (kt << 1) + (j >> 1);
                unsigned ad = Ab + (((row << 5) + ((quad ^ (row & 7)) << 2)) << 2);
                LDMX4(a, ad);
            }
            #pragma unroll
            for (int ni = 0; ni < 8; ni++) {
                int n = (ni << 3) + g;
                unsigned b[2];
                b[0] = __float_as_uint(Bb[n * 33 + (kt << 3) + t]);
                b[1] = __float_as_uint(Bb[n * 33 + (kt << 3) + t + 4]);
                MMA_TF32(acc[ni], a, b);
            }
        }
    };

    fetch(0);
    int nch = K >> 5;
    for (int ch = 0; ch < nch; ch++) {
        stash(ch & 1);
        __syncthreads();
        if (ch + 1 < nch) fetch((ch + 1) << 5);
        compute(ch & 1);
        __syncthreads();
    }

    int g = lane >> 2, t = lane & 3;
    #pragma unroll
    for (int half = 0; half < 2; half++) {
        int r = row0 + (wm << 4) + (half << 3) + g;
        #pragma unroll
        for (int ni = 0; ni < 8; ni++) {
            int c = (ni << 3) + (t << 1);
            *(float2*)(C + (long long)r * 64 + c) =
                make_float2(acc[ni][half * 2] * alpha, acc[ni][half * 2 + 1] * alpha);
        }
    }
}

// ========== fAV: flash-style AV = softmax(QL @ K^T) @ V, split-KV ==========
// grid (8 splits, 2 row-tiles, 16 bh); 1 CTA/SM; writes UNNORMALIZED partials
// AVp + per-row (m, s) stats into RSs; avreduce does the exact weighted merge.
// smem (floats): Q 0..8192 | K 8192..16384 | V 16384..24768 (n*131+k) |
//                P 24832..41216 | redm 41216 | reds 41472 | stm 41728 |
//                sts 41856 | rsc 41984  (total 42112 f = 168448 B)
__global__ void __launch_bounds__(256, 1) fAV_k(
    const float* __restrict__ QKV, const float* __restrict__ QL,
    float* __restrict__ AVp, float2* __restrict__ RSs)
{
    extern __shared__ float fs[];
    int tid = threadIdx.x, lane = tid & 31, wid = tid >> 5;
    int sp = blockIdx.x, rt = blockIdx.y, bh = blockIdx.z;
    int b = bh >> 3, h = bh & 7;
    const float* Qb = QL + ((long long)bh * LM + rt * 128) * DH;
    const float* Kb = QKV + (long long)(b * NF + sp * 1024) * QD + 512 + h * 64;
    const float* Vb = QKV + (long long)(b * NF + sp * 1024) * QD + 1024 + h * 64;
    AVp += ((long long)(bh * KSPL + sp) * LM + rt * 128) * DH;
    RSs += (long long)(bh * KSPL + sp) * LM + rt * 128;

    unsigned sbase;
    asm("{ .reg .u64 t; cvta.to.shared.u64 t, %1; cvt.u32.u64 %0, t; }"
        : "=r"(sbase) : "l"(fs));
    const unsigned Qoff = 0, Koff = 8192u, Voff = 16384u, Poff = 24832u;
    float* redm = fs + 41216;
    float* reds = fs + 41472;
    float* stm  = fs + 41728;
    float* sts  = fs + 41856;
    float* rsc  = fs + 41984;

    int wm = wid & 3, wn = wid >> 2;
    int j = lane >> 3, rho = lane & 7;
    int g = lane >> 2, t4 = lane & 3;

    // stage QL tile (128x64, 2 swizzled 32k chunks) + init running stats
    #pragma unroll
    for (int it = 0; it < 8; it++) {
        int idx = (it << 8) + tid;
        int q4 = idx & 15, r = idx >> 4;
        float4 v = *(const float4*)(Qb + (long long)r * 64 + (q4 << 2));
        int ch = q4 >> 3, q = q4 & 7;
        *(float4*)&fs[Qoff + (ch << 12) + (r << 5) + ((q ^ (r & 7)) << 2)] = v;
    }
    if (tid < 128) { stm[tid] = -1e30f; sts[tid] = 0.f; }

    float acc2[8][4];
    #pragma unroll
    for (int ni = 0; ni < 8; ni++)
        #pragma unroll
        for (int q = 0; q < 4; q++) acc2[ni][q] = 0.f;

    __syncthreads();

    for (int st = 0; st < 8; st++) {
        // ---- stage K subtile (128x64, swizzled) + V subtile (n*131+k) ----
        #pragma unroll
        for (int it = 0; it < 8; it++) {
            int idx = (it << 8) + tid;
            int q4 = idx & 15, n = idx >> 4;
            float4 v = *(const float4*)(Kb + (long long)(st * 128 + n) * QD + (q4 << 2));
            int ch = q4 >> 3, q = q4 & 7;
            *(float4*)&fs[Koff + (ch << 12) + (n << 5) + ((q ^ (n & 7)) << 2)] = v;
        }
        #pragma unroll
        for (int it = 0; it < 32; it++) {
            int idx = (it << 8) + tid;
            int k = idx >> 6, n = idx & 63;
            fs[Voff + n * 131 + k] = tf32f(Vb[(long long)(st * 128 + k) * QD + n]);
        }
        __syncthreads();

        // ---- phase 1: S = QL @ K^T (128 x 128) ----
        float acc1[2][8][4];
        #pragma unroll
        for (int mi = 0; mi < 2; mi++)
            #pragma unroll
            for (int ni = 0; ni < 8; ni++)
                #pragma unroll
                for (int q = 0; q < 4; q++) acc1[mi][ni][q] = 0.f;

        #pragma unroll
        for (int ch = 0; ch < 2; ch++) {
            #pragma unroll
            for (int kt = 0; kt < 4; kt++) {
                unsigned a[2][4];
                #pragma unroll
                for (int mi = 0; mi < 2; mi++) {
                    int row = (wm << 5) + (mi << 4) + ((j & 1) << 3) + rho;
                    int quad = (kt << 1) + (j >> 1);
                    LDMX4(a[mi], sbase + ((Qoff + (ch << 12) + (row << 5) + ((quad ^ (row & 7)) << 2)) << 2));
                }
                unsigned bfr[8][2];
                #pragma unroll
                for (int np = 0; np < 4; np++) {
                    int row = (((wn << 3) + (np << 1) + (j >> 1)) << 3) + rho;
                    int quad = (kt << 1) + (j & 1);
                    unsigned v[4];
                    LDMX4(v, sbase + ((Koff + (ch << 12) + (row << 5) + ((quad ^ (row & 7)) << 2)) << 2));
                    bfr[np * 2][0] = v[0]; bfr[np * 2][1] = v[1];
                    bfr[np * 2 + 1][0] = v[2]; bfr[np * 2 + 1][1] = v[3];
                }
                #pragma unroll
                for (int mi = 0; mi < 2; mi++)
                    #pragma unroll
                    for (int ni = 0; ni < 8; ni++)
                        MMA_TF32(acc1[mi][ni], a[mi], bfr[ni]);
            }
        }

        // ---- chunk stats: per-row (m, s) from accumulators ----
        float rowm[2][2];
        #pragma unroll
        for (int mi = 0; mi < 2; mi++)
            #pragma unroll
            for (int half = 0; half < 2; half++) {
                float m = -1e30f;
                #pragma unroll
                for (int ni = 0; ni < 8; ni++)
                    m = fmaxf(m, fmaxf(acc1[mi][ni][half * 2], acc1[mi][ni][half * 2 + 1]));
                m = fmaxf(m, __shfl_xor_sync(0xffffffffu, m, 1));
                m = fmaxf(m, __shfl_xor_sync(0xffffffffu, m, 2));
                if (t4 == 0) {
                    int rl = (wm << 5) + (mi << 4) + (half << 3) + g;
                    redm[rl * 2 + wn] = m;
                }
            }
        __syncthreads();
        #pragma unroll
        for (int mi = 0; mi < 2; mi++)
            #pragma unroll
            for (int half = 0; half < 2; half++) {
                int rl = (wm << 5) + (mi << 4) + (half << 3) + g;
                rowm[mi][half] = fmaxf(redm[rl * 2], redm[rl * 2 + 1]);
            }
        #pragma unroll
        for (int mi = 0; mi < 2; mi++)
            #pragma unroll
            for (int half = 0; half < 2; half++) {
                float m = rowm[mi][half];
                float s = 0.f;
                #pragma unroll
                for (int ni = 0; ni < 8; ni++)
                    s += __expf(acc1[mi][ni][half * 2] - m) + __expf(acc1[mi][ni][half * 2 + 1] - m);
                s += __shfl_xor_sync(0xffffffffu, s, 1);
                s += __shfl_xor_sync(0xffffffffu, s, 2);
                if (t4 == 0) {
                    int rl = (wm << 5) + (mi << 4) + (half << 3) + g;
                    reds[rl * 2 + wn] = s;
                }
            }
        __syncthreads();

        // ---- online combine (tid < 128) ----
        if (tid < 128) {
            float cm = fmaxf(redm[tid * 2], redm[tid * 2 + 1]);
            float cs = reds[tid * 2] + reds[tid * 2 + 1];
            float mo = stm[tid];
            float mn = fmaxf(mo, cm);
            float rr = __expf(mo - mn);
            rsc[tid] = rr;
            sts[tid] = sts[tid] * rr + cs * __expf(cm - mn);
            stm[tid] = mn;
        }
        __syncthreads();

        // ---- P = exp(S - m_new) into Psm; rescale acc2 ----
        #pragma unroll
        for (int mi = 0; mi < 2; mi++)
            #pragma unroll
            for (int half = 0; half < 2; half++) {
                int r1 = (wm << 5) + (mi << 4) + (half << 3) + g;
                float mn = stm[r1];
                #pragma unroll
                for (int ni = 0; ni < 8; ni++) {
                    int c = (wn << 6) + (ni << 3) + (t4 << 1);
                    int cc = c >> 5, q = (c & 31) >> 2, e = c & 3;
                    *(float2*)&fs[Poff + (cc << 12) + (r1 << 5) + ((q ^ (r1 & 7)) << 2) + e] =
                        make_float2(__expf(acc1[mi][ni][half * 2] - mn),
                                    __expf(acc1[mi][ni][half * 2 + 1] - mn));
                }
            }
        #pragma unroll
        for (int half = 0; half < 2; half++) {
            int r2 = (wid << 4) + (half << 3) + g;
            float rr = rsc[r2];
            #pragma unroll
            for (int ni = 0; ni < 8; ni++) {
                acc2[ni][half * 2]     *= rr;
                acc2[ni][half * 2 + 1] *= rr;
            }
        }
        __syncthreads();

        // ---- phase 2: acc2 += P @ V (128 x 64, K=128) ----
        #pragma unroll
        for (int cc = 0; cc < 4; cc++) {
            #pragma unroll
            for (int kt = 0; kt < 4; kt++) {
                unsigned a[4];
                {
                    int row = (wid << 4) + ((j & 1) << 3) + rho;
                    int quad = (kt << 1) + (j >> 1);
                    LDMX4(a, sbase + ((Poff + (cc << 12) + (row << 5) + ((quad ^ (row & 7)) << 2)) << 2));
                }
                #pragma unroll
                for (int ni = 0; ni < 8; ni++) {
                    int n = (ni << 3) + g;
                    unsigned bb2[2];
                    bb2[0] = __float_as_uint(fs[Voff + n * 131 + (cc << 5) + (kt << 3) + t4]);
                    bb2[1] = __float_as_uint(fs[Voff + n * 131 + (cc << 5) + (kt << 3) + t4 + 4]);
                    MMA_TF32(acc2[ni], a, bb2);
                }
            }
        }
        __syncthreads();
    }

    // ---- write unnormalized partial AV + stats ----
    #pragma unroll
    for (int half = 0; half < 2; half++) {
        int r = (wid << 4) + (half << 3) + g;
        #pragma unroll
        for (int ni = 0; ni < 8; ni++) {
            int c = (ni << 3) + (t4 << 1);
            *(float2*)(AVp + (long long)r * 64 + c) =
                make_float2(acc2[ni][half * 2], acc2[ni][half * 2 + 1]);
        }
    }
    if (tid < 128) RSs[tid] = make_float2(stm[tid], sts[tid]);
}

// ---------------- split-KV weighted reduce: AV = lse-merge(AVp) -------------
__global__ void __launch_bounds__(256) avreduce_k(const float2* __restrict__ RSs)
{
    int idx = blockIdx.x * 256 + threadIdx.x;     // NBH*LM*DH = 262144
    int bh = idx >> 14;
    int r  = (idx >> 6) & 255;
    int d  = idx & 63;
    float2 st[KSPL];
    float M = -1e30f;
    #pragma unroll
    for (int sp = 0; sp < KSPL; sp++) {
        st[sp] = RSs[(long long)(bh * KSPL + sp) * LM + r];
        M = fmaxf(M, st[sp].x);
    }
    float num = 0.f, den = 0.f;
    #pragma unroll
    for (int sp = 0; sp < KSPL; sp++) {
        float w = __expf(st[sp].x - M);
        num += w * g_AVp[((long long)(bh * KSPL + sp) * LM + r) * DH + d];
        den += w * st[sp].y;
    }
    g_AV[idx] = num / den;
}

// ========== fOH: fused OH = softmax(Q @ KL^T) @ ZAV (exact, per-CTA) ========
__global__ void __launch_bounds__(256, 1) fOH_k(
    const float* __restrict__ QKV, const float* __restrict__ KL,
    const float* __restrict__ ZAV, float* __restrict__ OH)
{
    extern __shared__ float fs[];
    int tid = threadIdx.x, lane = tid & 31, wid = tid >> 5;
    int row0 = blockIdx.x << 7;
    int bh = blockIdx.y;
    int b = bh >> 3, h = bh & 7;
    const float* Qb = QKV + ((long long)b * NF) * QD + h * 64;
    KL  += (long long)bh * LM * DH;
    ZAV += (long long)bh * LM * DH;
    OH  += (long long)bh * NF * DH;

    unsigned sbase;
    asm("{ .reg .u64 t; cvta.to.shared.u64 t, %1; cvt.u32.u64 %0, t; }"
        : "=r"(sbase) : "l"(fs));
    const unsigned Soff = 0, R1off = 32768u, Qoff = 49152u;
    float* redm = fs + 50176;
    float* reds = fs + 50688;
    float* stm  = fs + 51200;
    float* sti  = fs + 51328;

    {
        #pragma unroll
        for (int it = 0; it < 8; it++) {
            int idx = (it << 8) + tid;
            int q4 = idx & 15, r = idx >> 4;
            float4 v = *(const float4*)(Qb + (long long)(row0 + r) * QD + (q4 << 2));
            int ch = q4 >> 3, q = q4 & 7;
            *(float4*)&fs[Qoff + (ch << 12) + (r << 5) + ((q ^ (r & 7)) << 2)] = v;
        }
        #pragma unroll
        for (int it = 0; it < 16; it++) {
            int idx = (it << 8) + tid;
            int q = idx & 7, n = (idx >> 3) & 255, ch = idx >> 11;
            float4 v = *(const float4*)(KL + (long long)n * 64 + (ch << 5) + (q << 2));
            *(float4*)&fs[R1off + (ch << 13) + (n << 5) + ((q ^ (n & 7)) << 2)] = v;
        }
    }
    __syncthreads();

    int wm = wid & 3, wn = wid >> 2;
    int j = lane >> 3, rho = lane & 7;
    int g = lane >> 2, t4 = lane & 3;
    float acc1[2][2][8][4];
    #pragma unroll
    for (int nh = 0; nh < 2; nh++)
        #pragma unroll
        for (int mi = 0; mi < 2; mi++)
            #pragma unroll
            for (int ni = 0; ni < 8; ni++)
                #pragma unroll
                for (int q = 0; q < 4; q++) acc1[nh][mi][ni][q] = 0.f;

    #pragma unroll
    for (int ch = 0; ch < 2; ch++) {
        #pragma unroll
        for (int kt = 0; kt < 4; kt++) {
            unsigned a[2][4];
            #pragma unroll
            for (int mi = 0; mi < 2; mi++) {
                int row = (wm << 5) + (mi << 4) + ((j & 1) << 3) + rho;
                int quad = (kt << 1) + (j >> 1);
                LDMX4(a[mi], sbase + ((Qoff + (ch << 12) + (row << 5) + ((quad ^ (row & 7)) << 2)) << 2));
            }
            #pragma unroll
            for (int nh = 0; nh < 2; nh++) {
                unsigned bfr[8][2];
                #pragma unroll
                for (int np = 0; np < 4; np++) {
                    int row = (nh << 7) + ((((wn << 3) + (np << 1) + (j >> 1))) << 3) + rho;
                    int quad = (kt << 1) + (j & 1);
                    unsigned v[4];
                    LDMX4(v, sbase + ((R1off + (ch << 13) + (row << 5) + ((quad ^ (row & 7)) << 2)) << 2));
                    bfr[np * 2][0] = v[0]; bfr[np * 2][1] = v[1];
                    bfr[np * 2 + 1][0] = v[2]; bfr[np * 2 + 1][1] = v[3];
                }
                #pragma unroll
                for (int mi = 0; mi < 2; mi++)
                    #pragma unroll
                    for (int ni = 0; ni < 8; ni++)
                        MMA_TF32(acc1[nh][mi][ni], a[mi], bfr[ni]);
            }
        }
    }
    __syncthreads();

    #pragma unroll
    for (int nh = 0; nh < 2; nh++) {
        #pragma unroll
        for (int mi = 0; mi < 2; mi++) {
            #pragma unroll
            for (int half = 0; half < 2; half++) {
                int r = (wm << 5) + (mi << 4) + (half << 3) + g;
                #pragma unroll
                for (int ni = 0; ni < 8; ni++) {
                    int c = (nh << 7) + (wn << 6) + (ni << 3) + (t4 << 1);
                    int cc = c >> 5, q = (c & 31) >> 2, e = c & 3;
                    *(float2*)&fs[Soff + (cc << 12) + (r << 5) + ((q ^ (r & 7)) << 2) + e] =
                        make_float2(acc1[nh][mi][ni][half * 2], acc1[nh][mi][ni][half * 2 + 1]);
                }
            }
        }
    }
    #pragma unroll
    for (int nh = 0; nh < 2; nh++)
        #pragma unroll
        for (int mi = 0; mi < 2; mi++)
            #pragma unroll
            for (int half = 0; half < 2; half++) {
                float m = -1e30f;
                #pragma unroll
                for (int ni = 0; ni < 8; ni++)
                    m = fmaxf(m, fmaxf(acc1[nh][mi][ni][half * 2], acc1[nh][mi][ni][half * 2 + 1]));
                m = fmaxf(m, __shfl_xor_sync(0xffffffffu, m, 1));
                m = fmaxf(m, __shfl_xor_sync(0xffffffffu, m, 2));
                float s = 0.f;
                #pragma unroll
                for (int ni = 0; ni < 8; ni++)
                    s += __expf(acc1[nh][mi][ni][half * 2] - m) + __expf(acc1[nh][mi][ni][half * 2 + 1] - m);
                s += __shfl_xor_sync(0xffffffffu, s, 1);
                s += __shfl_xor_sync(0xffffffffu, s, 2);
                if (t4 == 0) {
                    int rl = (wm << 5) + (mi << 4) + (half << 3) + g;
                    redm[rl * 4 + nh * 2 + wn] = m;
                    reds[rl * 4 + nh * 2 + wn] = s;
                }
            }
    __syncthreads();

    if (tid < 128) {
        float m0 = redm[tid * 4], m1 = redm[tid * 4 + 1];
        float m2 = redm[tid * 4 + 2], m3 = redm[tid * 4 + 3];
        float m = fmaxf(fmaxf(m0, m1), fmaxf(m2, m3));
        float s = reds[tid * 4] * __expf(m0 - m) + reds[tid * 4 + 1] * __expf(m1 - m)
                + reds[tid * 4 + 2] * __expf(m2 - m) + reds[tid * 4 + 3] * __expf(m3 - m);
        stm[tid] = m;
        sti[tid] = 1.f / s;
    }
    __syncthreads();

    #pragma unroll
    for (int it = 0; it < 64; it++) {
        int idx = (it << 8) + tid;
        int k = idx >> 6, n = idx & 63;
        fs[R1off + n * 259 + k] = ZAV[(long long)k * 64 + n];
    }
    #pragma unroll
    for (int it = 0; it < 128; it++) {
        int i = (it << 8) + tid;
        int r = (i & 4095) >> 5;
        float v = fs[Soff + i];
        fs[Soff + i] = __expf(v - stm[r]) * sti[r];
    }
    __syncthreads();

    float acc2[8][4];
    #pragma unroll
    for (int ni = 0; ni < 8; ni++)
        #pragma unroll
        for (int q = 0; q < 4; q++) acc2[ni][q] = 0.f;

    #pragma unroll
    for (int cc = 0; cc < 8; cc++) {
        #pragma unroll
        for (int kt = 0; kt < 4; kt++) {
            unsigned a[4];
            {
                int row = (wid << 4) + ((j & 1) << 3) + rho;
                int quad = (kt << 1) + (j >> 1);
                LDMX4(a, sbase + ((Soff + (cc << 12) + (row << 5) + ((quad ^ (row & 7)) << 2)) << 2));
            }
            #pragma unroll
            for (int ni = 0; ni < 8; ni++) {
                int n = (ni << 3) + g;
                unsigned b[2];
                b[0] = __float_as_uint(fs[R1off + n * 259 + (cc << 5) + (kt << 3) + t4]);
                b[1] = __float_as_uint(fs[R1off + n * 259 + (cc << 5) + (kt << 3) + t4 + 4]);
                MMA_TF32(acc2[ni], a, b);
            }
        }
    }

    #pragma unroll
    for (int half = 0; half < 2; half++) {
        int r = row0 + (wid << 4) + (half << 3) + g;
        #pragma unroll
        for (int ni = 0; ni < 8; ni++) {
            int c = (ni << 3) + (t4 << 1);
            *(float2*)(OH + (long long)r * 64 + c) =
                make_float2(acc2[ni][half * 2], acc2[ni][half * 2 + 1]);
        }
    }
}

// ===================== pinv: persistent chain kernel ========================
__device__ __forceinline__ void gbar(unsigned target) {
    __syncthreads();
    if (threadIdx.x == 0) {
        __threadfence();
        atomicAdd(&g_bar, 1u);
        while (*(volatile unsigned*)&g_bar < target) {}
        __threadfence();
    }
    __syncthreads();
}

__device__ void pg_tile(const float* __restrict__ Ag, const float* __restrict__ Bg,
                        float* __restrict__ Cg, float alpha, int bmode, float bd,
                        float* ps)
{
    int bid = blockIdx.x;
    int tid = threadIdx.x;
    int lane = tid & 31, wid = tid >> 5;
    int wm = wid & 3, wn = wid >> 2;
    int col0 = (bid & 1) << 7;
    int row0 = ((bid >> 1) & 3) << 6;
    long long zo = (long long)(bid >> 3) << 16;
    Ag += zo; Bg += zo; Cg += zo;

    float acc[8][4];
    #pragma unroll
    for (int ni = 0; ni < 8; ni++)
        #pragma unroll
        for (int q = 0; q < 4; q++) acc[ni][q] = 0.f;

    int ar = tid >> 2, aq = tid & 3;
    int bn = tid & 127, bkh = tid >> 7;

    float4 pa;
    float pbv[8];

    auto fetch = [&](int k0) {
        pa = *(const float4*)(Ag + ((long long)(row0 + ar) << 8) + k0 + (aq << 2));
        #pragma unroll
        for (int j = 0; j < 8; j++) {
            int gk = k0 + (bkh << 3) + j;
            int gn = col0 + bn;
            float v = Bg[((long long)gk << 8) + gn];
            if (bmode) v = (gk == gn ? bd : 0.f) - v;
            pbv[j] = v;
        }
    };

    auto stash = [&](int s) {
        float* Sb = ps + s * 7680;
        float4 h, l;
        h.x = tf32f(pa.x); h.y = tf32f(pa.y); h.z = tf32f(pa.z); h.w = tf32f(pa.w);
        l.x = tf32f(pa.x - h.x); l.y = tf32f(pa.y - h.y);
        l.z = tf32f(pa.z - h.z); l.w = tf32f(pa.w - h.w);
        *(float4*)&Sb[ar * 20 + (aq << 2)] = h;
        *(float4*)&Sb[1280 + ar * 20 + (aq << 2)] = l;
        float4 bh0, bh1, bl0, bl1;
        bh0.x = tf32f(pbv[0]); bh0.y = tf32f(pbv[1]); bh0.z = tf32f(pbv[2]); bh0.w = tf32f(pbv[3]);
        bh1.x = tf32f(pbv[4]); bh1.y = tf32f(pbv[5]); bh1.z = tf32f(pbv[6]); bh1.w = tf32f(pbv[7]);
        bl0.x = tf32f(pbv[0] - bh0.x); bl0.y = tf32f(pbv[1] - bh0.y);
        bl0.z = tf32f(pbv[2] - bh0.z); bl0.w = tf32f(pbv[3] - bh0.w);
        bl1.x = tf32f(pbv[4] - bh1.x); bl1.y = tf32f(pbv[5] - bh1.y);
        bl1.z = tf32f(pbv[6] - bh1.z); bl1.w = tf32f(pbv[7] - bh1.w);
        *(float4*)&Sb[2560 + bn * 20 + (bkh << 3)] = bh0;
        *(float4*)&Sb[2560 + bn * 20 + (bkh << 3) + 4] = bh1;
        *(float4*)&Sb[5120 + bn * 20 + (bkh << 3)] = bl0;
        *(float4*)&Sb[5120 + bn * 20 + (bkh << 3) + 4] = bl1;
    };

    auto compute = [&](int s) {
        const float* Sb = ps + s * 7680;
        int g = lane >> 2, t = lane & 3;
        #pragma unroll
        for (int kt = 0; kt < 2; kt++) {
            int kb = kt << 3;
            int m = (wm << 4) + g;
            unsigned ah[4], al[4];
            ah[0] = __float_as_uint(Sb[m * 20 + kb + t]);
            ah[1] = __float_as_uint(Sb[(m + 8) * 20 + kb + t]);
            ah[2] = __float_as_uint(Sb[m * 20 + kb + t + 4]);
            ah[3] = __float_as_uint(Sb[(m + 8) * 20 + kb + t + 4]);
            al[0] = __float_as_uint(Sb[1280 + m * 20 + kb + t]);
            al[1] = __float_as_uint(Sb[1280 + (m + 8) * 20 + kb + t]);
            al[2] = __float_as_uint(Sb[1280 + m * 20 + kb + t + 4]);
            al[3] = __float_as_uint(Sb[1280 + (m + 8) * 20 + kb + t + 4]);
            #pragma unroll
            for (int ni = 0; ni < 8; ni++) {
                int n = (wn << 6) + (ni << 3) + g;
                unsigned bh[2], bl[2];
                bh[0] = __float_as_uint(Sb[2560 + n * 20 + kb + t]);
                bh[1] = __float_as_uint(Sb[2560 + n * 20 + kb + t + 4]);
                bl[0] = __float_as_uint(Sb[5120 + n * 20 + kb + t]);
                bl[1] = __float_as_uint(Sb[5120 + n * 20 + kb + t + 4]);
                MMA_TF32(acc[ni], ah, bh);
                MMA_TF32(acc[ni], ah, bl);
                MMA_TF32(acc[ni], al, bh);
            }
        }
    };

    fetch(0);
    for (int ch = 0; ch < 16; ch++) {
        stash(ch & 1);
        __syncthreads();
        if (ch < 15) fetch((ch + 1) << 4);
        compute(ch & 1);
        __syncthreads();
    }

    int g = lane >> 2, t = lane & 3;
    #pragma unroll
    for (int half = 0; half < 2; half++) {
        int r = row0 + (wm << 4) + (half << 3) + g;
        #pragma unroll
        for (int ni = 0; ni < 8; ni++) {
            int c = col0 + (wn << 6) + (ni << 3) + (t << 1);
            *(float2*)(Cg + ((long long)r << 8) + c) =
                make_float2(acc[ni][half * 2] * alpha, acc[ni][half * 2 + 1] * alpha);
        }
    }
}

__global__ void __launch_bounds__(256) pinvchain_k()
{
    extern __shared__ float ps[];
    int bid = blockIdx.x;
    int tid = threadIdx.x;

    if (bid < 16) {
        const float* S = g_S2 + ((long long)bid << 16);
        float rs = 0.f, cs = 0.f;
        for (int j = 0; j < 256; j++) {
            rs += S[(tid << 8) + j];
            cs += S[(j << 8) + tid];
        }
        float rm = blockReduce(rs, true);
        float cm = blockReduce(cs, true);
        if (tid == 0) {
            atomicMax(&g_scale[0], __float_as_uint(rm));
            atomicMax(&g_scale[1], __float_as_uint(cm));
        }
    }
    gbar(128);

    {
        float inv = 1.0f / (__uint_as_float(g_scale[0]) * __uint_as_float(g_scale[1]));
        #pragma unroll
        for (int e = 0; e < 32; e++) {
            int idx = (bid << 13) + (e << 8) + tid;
            int z = idx >> 16, r = idx & 65535;
            int i = r >> 8, j = r & 255;
            g_Zb[((long long)z << 16) + (i << 8) + j] =
                g_S2[((long long)z << 16) + (j << 8) + i] * inv;
        }
    }
    gbar(256);

    unsigned t = 256;
    for (int it = 0; it < 6; it++) {
        float* Zi = (it & 1) ? g_Z2b : g_Zb;
        float* Zo = (it & 1) ? g_Zb : g_Z2b;
        pg_tile(g_S2, Zi, g_Pb, 1.f, 0, 0.f, ps);  t += 128; gbar(t);
        pg_tile(g_Pb, g_Pb, g_T2b, 1.f, 1, 7.f, ps);  t += 128; gbar(t);
        pg_tile(g_Pb, g_T2b, g_Tb, 1.f, 1, 15.f, ps);  t += 128; gbar(t);
        pg_tile(Zi, g_Tb, Zo, 0.25f, 1, 13.f, ps);  t += 128; gbar(t);
    }
}

__global__ void reset_k() { g_scale[0] = 0u; g_scale[1] = 0u; g_bar = 0u; }

// ------------------------- layernorm (rows of 512) --------------------------
__global__ void __launch_bounds__(256) ln_k(const float* __restrict__ X, float* __restrict__ Y,
                                            const float* __restrict__ g, const float* __restrict__ b)
{
    long long row = blockIdx.x;
    const float* x = X + row * DIMM;
    float* y = Y + row * DIMM;
    int t = threadIdx.x;
    float v0 = x[t], v1 = x[t + 256];
    float mu  = blockReduce(v0 + v1, false) * (1.f / 512.f);
    float d0 = v0 - mu, d1 = v1 - mu;
    float var = blockReduce(d0 * d0 + d1 * d1, false) * (1.f / 512.f);
    float inv = rsqrtf(var + 1e-5f);
    y[t]       = d0 * inv * g[t]       + b[t];
    y[t + 256] = d1 * inv * g[t + 256] + b[t + 256];
}

// ------------------------- softmax (S2 only) --------------------------------
__global__ void __launch_bounds__(256) softmax256_k(float* __restrict__ S)
{
    long long row = ((long long)blockIdx.x << 3) + (threadIdx.x >> 5);
    int lane = threadIdx.x & 31;
    float* s = S + (row << 8);
    float4 va = *(float4*)(s + (lane << 3));
    float4 vb = *(float4*)(s + (lane << 3) + 4);
    float m = fmaxf(fmaxf(fmaxf(va.x, va.y), fmaxf(va.z, va.w)),
                    fmaxf(fmaxf(vb.x, vb.y), fmaxf(vb.z, vb.w)));
    #pragma unroll
    for (int o = 16; o > 0; o >>= 1) m = fmaxf(m, __shfl_xor_sync(0xffffffffu, m, o));
    va.x = __expf(va.x - m); va.y = __expf(va.y - m); va.z = __expf(va.z - m); va.w = __expf(va.w - m);
    vb.x = __expf(vb.x - m); vb.y = __expf(vb.y - m); vb.z = __expf(vb.z - m); vb.w = __expf(vb.w - m);
    float sum = va.x + va.y + va.z + va.w + vb.x + vb.y + vb.z + vb.w;
    #pragma unroll
    for (int o = 16; o > 0; o >>= 1) sum += __shfl_xor_sync(0xffffffffu, sum, o);
    float inv = 1.f / sum;
    va.x *= inv; va.y *= inv; va.z *= inv; va.w *= inv;
    vb.x *= inv; vb.y *= inv; vb.z *= inv; vb.w *= inv;
    *(float4*)(s + (lane << 3)) = va;
    *(float4*)(s + (lane << 3) + 4) = vb;
}

// ------------------------- landmarks ----------------------------------------
__global__ void __launch_bounds__(64) landmark_k()
{
    int zz = blockIdx.x;
    int mi = zz & 255, bh = zz >> 8;
    int b = bh >> 3, h = bh & 7;
    int d = threadIdx.x;
    const float* base = g_QKV + (long long)(b * NF + mi * 32) * QD + h * 64 + d;
    float sq = 0.f, sk = 0.f;
    #pragma unroll 8
    for (int il = 0; il < 32; il++) {
        sq += base[(long long)il * QD];
        sk += base[(long long)il * QD + 512];
    }
    long long o = ((long long)bh * LM + mi) * DH + d;
    g_QL[o] = sq * (1.f / 32.f);
    g_KL[o] = sk * (1.f / 32.f);
}

// ------------------------- depthwise conv residual --------------------------
__global__ void __launch_bounds__(256) conv_k(const float* __restrict__ cw)
{
    __shared__ float sv[160 * 64];
    __shared__ float sw[KER];
    int tile = blockIdx.x;
    int bh = blockIdx.y;
    int b = bh >> 3, h = bh & 7;
    int n0 = tile * 128;
    int t = threadIdx.x;
    if (t < KER) sw[t] = cw[h * KER + t];
    for (int idx = t; idx < 160 * 64; idx += 256) {
        int r = idx >> 6, d = idx & 63;
        int nn = n0 - 16 + r;
        float v = 0.f;
        if (nn >= 0 && nn < NF) v = g_QKV[(long long)(b * NF + nn) * QD + 1024 + h * 64 + d];
        sv[idx] = v;
    }
    __syncthreads();
    int d = t & 63, r0 = t >> 6;
    for (int rr = r0; rr < 128; rr += 4) {
        float a = 0.f;
        #pragma unroll
        for (int k = 0; k < KER; k++) a += sv[(rr + k) * 64 + d] * sw[k];
        long long o = ((long long)bh * NF + n0 + rr) * DH + d;
        g_OH[o] += a;
    }
}

// ------------------------- final LN + head ----------------------------------
__global__ void __launch_bounds__(256) final_k(const float* __restrict__ fg, const float* __restrict__ fb,
                                               const float* __restrict__ w2, const float* __restrict__ b2,
                                               float* __restrict__ out)
{
    int b = blockIdx.x;
    const float* x = g_X + (long long)b * NF * DIMM;
    int t = threadIdx.x;
    float v0 = x[t], v1 = x[t + 256];
    float mu  = blockReduce(v0 + v1, false) * (1.f / 512.f);
    float d0 = v0 - mu, d1 = v1 - mu;
    float var = blockReduce(d0 * d0 + d1 * d1, false) * (1.f / 512.f);
    float inv = rsqrtf(var + 1e-5f);
    float n0 = d0 * inv * fg[t]       + fb[t];
    float n1 = d1 * inv * fg[t + 256] + fb[t + 256];
    float p0 = n0 * w2[2 * t]     + n1 * w2[2 * (t + 256)];
    float p1 = n0 * w2[2 * t + 1] + n1 * w2[2 * (t + 256) + 1];
    p0 = blockReduce(p0, false);
    p1 = blockReduce(p1, false);
    if (t == 0) {
        out[b * 2 + 0] = p0 + b2[0];
        out[b * 2 + 1] = p1 + b2[1];
    }
}

// ------------------------- host orchestration -------------------------------
static inline void mgemm2(int M, int N, int K,
                          const float* A, int lda, long long sA1, long long sA2, int amode,
                          const float* BT, int ldbt, long long sBT1, long long sBT2,
                          float* C, int ldc, long long sC1, long long sC2,
                          int batch, int ep, const float* bias)
{
    dim3 g(N >> 7, (M + 127) >> 7, batch);
    cudaFuncSetAttribute(mgemm2_k<0>, cudaFuncAttributeMaxDynamicSharedMemorySize, 98304);
    mgemm2_k<0><<<g, 256, 98304>>>(M, K, A, lda, sA1, sA2, amode, BT, ldbt, sBT1, sBT2,
                                   C, ldc, sC1, sC2, ep, bias, nullptr, 0, 0);
}

static inline void agemm(int M, int K,
                         const float* A, int lda, long long sA1, long long sA2, long long sA3,
                         const float* B, int ldb, long long sB1, long long sB2, long long sB3,
                         float* C, long long sC1, long long sC2, long long sC3,
                         int SPLIT, int batchZ, float alpha,
                         const float2* rsA, long long rs1, long long rs2, int aexp)
{
    cudaFuncSetAttribute(agemm_k, cudaFuncAttributeMaxDynamicSharedMemorySize, 49664);
    dim3 g(1, M >> 7, batchZ);
    agemm_k<<<g, 256, 49664>>>(M, K, A, lda, sA1, sA2, sA3, B, ldb, sB1, sB2, sB3,
                               C, sC1, sC2, sC3, SPLIT, alpha, rsA, rs1, rs2, aexp);
}

extern "C" void kernel_launch(void* const* d_in, const int* in_sizes, int n_in,
                              void* d_out, int out_size)
{
    const float* h_in  = (const float*)d_in[0];
    const float* w1    = (const float*)d_in[1];
    const float* b1    = (const float*)d_in[2];
    const float* clst  = (const float*)d_in[3];
    const float* ln_g  = (const float*)d_in[4];
    const float* ln_b  = (const float*)d_in[5];
    const float* wqkv  = (const float*)d_in[6];
    const float* wout  = (const float*)d_in[7];
    const float* bout  = (const float*)d_in[8];
    const float* cw    = (const float*)d_in[9];
    const float* fg    = (const float*)d_in[10];
    const float* fb    = (const float*)d_in[11];
    const float* w2    = (const float*)d_in[12];
    const float* b2    = (const float*)d_in[13];
    float* out = (float*)d_out;

    float *X, *XN, *QKV, *QL, *KL, *S2p, *Z, *AV, *AVp, *ZAV, *OH, *WT;
    float2 *RS3, *RSp;
    cudaGetSymbolAddress((void**)&X,   g_X);
    cudaGetSymbolAddress((void**)&XN,  g_XN);
    cudaGetSymbolAddress((void**)&QKV, g_QKV);
    cudaGetSymbolAddress((void**)&QL,  g_QL);
    cudaGetSymbolAddress((void**)&KL,  g_KL);
    cudaGetSymbolAddress((void**)&S2p, g_S2);
    cudaGetSymbolAddress((void**)&Z,   g_Zb);
    cudaGetSymbolAddress((void**)&AV,  g_AV);
    cudaGetSymbolAddress((void**)&AVp, g_AVp);
    cudaGetSymbolAddress((void**)&ZAV, g_ZAV);
    cudaGetSymbolAddress((void**)&OH,  g_OH);
    cudaGetSymbolAddress((void**)&WT,  g_WT);
    cudaGetSymbolAddress((void**)&RS3, g_RS3);
    cudaGetSymbolAddress((void**)&RSp, g_RSp);

    const long long S2s = (long long)LM * LM;
    const long long AVs = (long long)LM * DH;

    cudaFuncSetAttribute(pinvchain_k, cudaFuncAttributeMaxDynamicSharedMemorySize, 61440);
    cudaFuncSetAttribute(fOH_k, cudaFuncAttributeMaxDynamicSharedMemorySize, 229376);
    cudaFuncSetAttribute(fAV_k, cudaFuncAttributeMaxDynamicSharedMemorySize, 168448);

    // #1: all weight transposes + cls fill
    transAll_k<<<2564, 256>>>(w1, wqkv, wout, clst);

    // #2: input projection
    mgemm2(NB * 8191, DIMM, 1024, h_in, 1024, 0, 0, 0, WT + OW1, 1024, 0, 0,
           X, DIMM, 0, 0, 1, EP_RELU_REMAP, b1);

    for (int L = 0; L < 2; L++) {
        // #3 (L=0): layernorm
        ln_k<<<TOT, 256>>>(X, XN, ln_g + L * DIMM, ln_b + L * DIMM);

        // #4 (L=0): qkv GEMM  <-- ncu capture slot
        mgemm2(TOT, QD, DIMM, XN, DIMM, 0, 0, 0, WT + OQKV(L), DIMM, 0, 0,
               QKV, QD, 0, 0, 1, EP_SCALEQ, nullptr);

        landmark_k<<<NBH * LM, 64>>>();

        // sim2 = QL @ KL^T, softmax
        mgemm2(LM, LM, DH, QL, DH, 8 * AVs, AVs, 0, KL, DH, 8 * AVs, AVs,
               S2p, LM, 8 * S2s, S2s, NBH, EP_NONE, nullptr);
        softmax256_k<<<NBH * LM / 8, 256>>>(S2p);

        // Moore-Penrose pinv of S2 -> Z : persistent chain
        reset_k<<<1, 1>>>();
        pinvchain_k<<<128, 256, 61440>>>();

        // AV = softmax(QL @ K^T) @ V  (flash-style fused, split-KV 8)
        fAV_k<<<dim3(KSPL, 2, NBH), 256, 168448>>>(QKV, QL, AVp, RSp);
        avreduce_k<<<1024, 256>>>(RSp);

        // ZAV = Z @ AV  (tensor)
        agemm(LM, LM,
              Z, LM, 8 * S2s, S2s, 0,
              AV, DH, 8 * AVs, AVs, 0,
              ZAV, 8 * AVs, AVs, 0,
              1, NBH, 1.f, RS3, 0, 0, 0);

        // OH = softmax(Q @ KL^T) @ ZAV  (fully fused, exact softmax)
        fOH_k<<<dim3(NF / 128, NBH), 256, 229376>>>(QKV, KL, ZAV, OH);

        // OH += depthwise conv residual of V
        { dim3 g(NF / 128, NBH); conv_k<<<g, 256>>>(cw + L * NH * KER); }

        // X += OH(head-layout) @ Wout + bout
        mgemm2(TOT, DIMM, DIMM, OH, 0, 0, 0, 1, WT + OOUT(L), DIMM, 0, 0,
               X, DIMM, 0, 0, 1, EP_ADDBIAS, bout + L * DIMM);
    }

    final_k<<<NB, 256>>>(fg, fb, w2, b2, out);
}